// round 1
// baseline (speedup 1.0000x reference)
#include <cuda_runtime.h>
#include <math.h>

#define NN 20000
#define NE 640000

// ---------------- scratch (device globals; no allocation at runtime) ----------------
__device__ __align__(16) float g_xenc[NN * 64];   // encoded nodes
__device__ __align__(16) float g_x1[NN * 64];     // conv0 output (pre-res+ LN)
__device__ __align__(16) float g_h1[NN * 64];     // relu(LN(x1)) = conv1 node input
__device__ __align__(16) float g_Pa[NN * 128];    // per-node dst-part of W1 (+b1)
__device__ __align__(16) float g_Pb[NN * 128];    // per-node src-part of W1
__device__ __align__(16) float g_nd0[NN * 128];   // conv0 (num,den) interleaved per channel
__device__ __align__(16) float g_nd1[NN * 128];   // conv1 (num,den)
__device__ __align__(16) float g_msg0[(size_t)NE * 64]; // conv0 raw messages (edge feats for conv1)

static __device__ __forceinline__ float wsum(float v) {
#pragma unroll
    for (int o = 16; o; o >>= 1) v += __shfl_xor_sync(0xffffffffu, v, o);
    return v;
}

// ---------------- zero num/den accumulators ----------------
__global__ void k_zero() {
    int i = blockIdx.x * blockDim.x + threadIdx.x;
    if (i < NN * 128 / 4) {
        float4 z = make_float4(0.f, 0.f, 0.f, 0.f);
        ((float4*)g_nd0)[i] = z;
        ((float4*)g_nd1)[i] = z;
    }
}

// ---------------- node encoder: x_enc = LN(x @ enc_w + enc_b) ----------------
__global__ void __launch_bounds__(256) k_encode(
    const float* __restrict__ x, const float* __restrict__ enc_w,
    const float* __restrict__ enc_b, const float* __restrict__ enc_g,
    const float* __restrict__ enc_bb)
{
    extern __shared__ float sm[];            // enc_w: 96*64
    for (int i = threadIdx.x; i < 96 * 64; i += blockDim.x) sm[i] = enc_w[i];
    __syncthreads();
    int l = threadIdx.x & 31;
    int warp = (blockIdx.x * blockDim.x + threadIdx.x) >> 5;
    int nwarps = (gridDim.x * blockDim.x) >> 5;
    float b0 = enc_b[l], b1v = enc_b[l + 32];
    float g0 = enc_g[l], g1 = enc_g[l + 32];
    float bb0 = enc_bb[l], bb1 = enc_bb[l + 32];
    for (int n = warp; n < NN; n += nwarps) {
        float xa = x[(size_t)n * 96 + l];
        float xb = x[(size_t)n * 96 + 32 + l];
        float xc = x[(size_t)n * 96 + 64 + l];
        float z0 = b0, z1 = b1v;
#pragma unroll 8
        for (int k = 0; k < 32; k++) {
            float xk = __shfl_sync(0xffffffffu, xa, k);
            z0 = fmaf(xk, sm[k * 64 + l], z0);
            z1 = fmaf(xk, sm[k * 64 + l + 32], z1);
        }
#pragma unroll 8
        for (int k = 0; k < 32; k++) {
            float xk = __shfl_sync(0xffffffffu, xb, k);
            z0 = fmaf(xk, sm[(k + 32) * 64 + l], z0);
            z1 = fmaf(xk, sm[(k + 32) * 64 + l + 32], z1);
        }
#pragma unroll 8
        for (int k = 0; k < 32; k++) {
            float xk = __shfl_sync(0xffffffffu, xc, k);
            z0 = fmaf(xk, sm[(k + 64) * 64 + l], z0);
            z1 = fmaf(xk, sm[(k + 64) * 64 + l + 32], z1);
        }
        float mu = wsum(z0 + z1) * (1.f / 64.f);
        float sq = wsum(z0 * z0 + z1 * z1) * (1.f / 64.f);
        float rs = rsqrtf(sq - mu * mu + 1e-5f);
        g_xenc[n * 64 + l]      = (z0 - mu) * rs * g0 + bb0;
        g_xenc[n * 64 + l + 32] = (z1 - mu) * rs * g1 + bb1;
    }
}

// ---------------- Pa = xin @ W1[0:64] + b1 ; Pb = xin @ W1[64:128] ----------------
__global__ void __launch_bounds__(256) k_prep(
    int use_h, const float* __restrict__ w1, const float* __restrict__ b1)
{
    extern __shared__ float sm[];            // w1 rows 0..127: 128*128
    for (int i = threadIdx.x; i < 128 * 128; i += blockDim.x) sm[i] = w1[i];
    __syncthreads();
    const float* xin = use_h ? g_h1 : g_xenc;
    int l = threadIdx.x & 31;
    int warp = (blockIdx.x * blockDim.x + threadIdx.x) >> 5;
    int nwarps = (gridDim.x * blockDim.x) >> 5;
    float4 bv = *(const float4*)(b1 + 4 * l);
    for (int n = warp; n < NN; n += nwarps) {
        float x0 = xin[n * 64 + l], x1 = xin[n * 64 + 32 + l];
        float4 pa = bv;
        float4 pb = make_float4(0.f, 0.f, 0.f, 0.f);
#pragma unroll 8
        for (int k = 0; k < 32; k++) {
            float xk = __shfl_sync(0xffffffffu, x0, k);
            float4 wa = *(const float4*)(sm + k * 128 + 4 * l);
            float4 wb = *(const float4*)(sm + (k + 64) * 128 + 4 * l);
            pa.x = fmaf(xk, wa.x, pa.x); pa.y = fmaf(xk, wa.y, pa.y);
            pa.z = fmaf(xk, wa.z, pa.z); pa.w = fmaf(xk, wa.w, pa.w);
            pb.x = fmaf(xk, wb.x, pb.x); pb.y = fmaf(xk, wb.y, pb.y);
            pb.z = fmaf(xk, wb.z, pb.z); pb.w = fmaf(xk, wb.w, pb.w);
        }
#pragma unroll 8
        for (int k = 0; k < 32; k++) {
            float xk = __shfl_sync(0xffffffffu, x1, k);
            float4 wa = *(const float4*)(sm + (k + 32) * 128 + 4 * l);
            float4 wb = *(const float4*)(sm + (k + 96) * 128 + 4 * l);
            pa.x = fmaf(xk, wa.x, pa.x); pa.y = fmaf(xk, wa.y, pa.y);
            pa.z = fmaf(xk, wa.z, pa.z); pa.w = fmaf(xk, wa.w, pa.w);
            pb.x = fmaf(xk, wb.x, pb.x); pb.y = fmaf(xk, wb.y, pb.y);
            pb.z = fmaf(xk, wb.z, pb.z); pb.w = fmaf(xk, wb.w, pb.w);
        }
        *(float4*)(g_Pa + (size_t)n * 128 + 4 * l) = pa;
        *(float4*)(g_Pb + (size_t)n * 128 + 4 * l) = pb;
    }
}

// ---------------- conv0 edge pass ----------------
// Per edge: ea = LN(edge_attr @ eenc_w + eenc_b); h = relu(Pa[dst]+Pb[src]+ea@W1c);
// msg = h@W2 + b2; e = exp(msg*t); red num/den; store msg.
// One warp handles 2 edges (amortize smem weight reads).
__global__ void __launch_bounds__(256) k_edge0(
    const int* __restrict__ ei, const float* __restrict__ eattr,
    const float* __restrict__ eenc_w, const float* __restrict__ eenc_b,
    const float* __restrict__ eenc_g, const float* __restrict__ eenc_bb,
    const float* __restrict__ w1, const float* __restrict__ w2,
    const float* __restrict__ b2, const float* __restrict__ tptr)
{
    extern __shared__ float sm[];
    float* sew = sm;                 // 16*64   = 1024
    float* sw1 = sm + 1024;          // 64*128  = 8192 (W1 rows 128..191)
    float* sw2 = sw1 + 8192;         // 128*64  = 8192
    float* sps = sw2 + 8192;         // eenc_b(64) eenc_g(64) eenc_bb(64) b2(64)
    for (int i = threadIdx.x; i < 1024; i += blockDim.x) sew[i] = eenc_w[i];
    for (int i = threadIdx.x; i < 8192; i += blockDim.x) {
        sw1[i] = w1[128 * 128 + i];
        sw2[i] = w2[i];
    }
    if (threadIdx.x < 64) {
        sps[threadIdx.x]       = eenc_b[threadIdx.x];
        sps[64 + threadIdx.x]  = eenc_g[threadIdx.x];
        sps[128 + threadIdx.x] = eenc_bb[threadIdx.x];
        sps[192 + threadIdx.x] = b2[threadIdx.x];
    }
    __syncthreads();
    float t = tptr[0];
    int l = threadIdx.x & 31;
    int warp = (blockIdx.x * blockDim.x + threadIdx.x) >> 5;
    int nwarps = (gridDim.x * blockDim.x) >> 5;
    const int* src = ei;
    const int* dst = ei + NE;

    for (int p = warp; p < NE / 2; p += nwarps) {
        int e0 = 2 * p, e1 = 2 * p + 1;
        int s0 = src[e0], d0 = dst[e0], s1 = src[e1], d1 = dst[e1];
        // gathers (L2-resident tables), issue early
        float4 pa0 = *(const float4*)(g_Pa + (size_t)d0 * 128 + 4 * l);
        float4 pb0 = *(const float4*)(g_Pb + (size_t)s0 * 128 + 4 * l);
        float4 pa1 = *(const float4*)(g_Pa + (size_t)d1 * 128 + 4 * l);
        float4 pb1 = *(const float4*)(g_Pb + (size_t)s1 * 128 + 4 * l);
        // edge attrs: lanes 0-15 -> edge0, 16-31 -> edge1 (contiguous 128B)
        float a = (l < 16) ? eattr[(size_t)e0 * 16 + l] : eattr[(size_t)e1 * 16 + (l - 16)];
        // edge encoder linear
        float z00 = sps[l], z01 = sps[l + 32];
        float z10 = z00, z11 = z01;
#pragma unroll
        for (int k = 0; k < 16; k++) {
            float a0 = __shfl_sync(0xffffffffu, a, k);
            float a1 = __shfl_sync(0xffffffffu, a, k + 16);
            float w0 = sew[k * 64 + l], wv = sew[k * 64 + l + 32];
            z00 = fmaf(a0, w0, z00); z01 = fmaf(a0, wv, z01);
            z10 = fmaf(a1, w0, z10); z11 = fmaf(a1, wv, z11);
        }
        // LN (both edges)
        float mu0 = wsum(z00 + z01) * (1.f / 64.f);
        float sq0 = wsum(z00 * z00 + z01 * z01) * (1.f / 64.f);
        float rs0 = rsqrtf(sq0 - mu0 * mu0 + 1e-5f);
        float ea00 = (z00 - mu0) * rs0 * sps[64 + l] + sps[128 + l];
        float ea01 = (z01 - mu0) * rs0 * sps[64 + l + 32] + sps[128 + l + 32];
        float mu1 = wsum(z10 + z11) * (1.f / 64.f);
        float sq1 = wsum(z10 * z10 + z11 * z11) * (1.f / 64.f);
        float rs1 = rsqrtf(sq1 - mu1 * mu1 + 1e-5f);
        float ea10 = (z10 - mu1) * rs1 * sps[64 + l] + sps[128 + l];
        float ea11 = (z11 - mu1) * rs1 * sps[64 + l + 32] + sps[128 + l + 32];
        // hidden: h = Pa[dst] + Pb[src] + ea @ W1c  (lane l owns hidden 4l..4l+3)
        float4 h0, h1;
        h0.x = pa0.x + pb0.x; h0.y = pa0.y + pb0.y; h0.z = pa0.z + pb0.z; h0.w = pa0.w + pb0.w;
        h1.x = pa1.x + pb1.x; h1.y = pa1.y + pb1.y; h1.z = pa1.z + pb1.z; h1.w = pa1.w + pb1.w;
#pragma unroll 8
        for (int k = 0; k < 32; k++) {
            float4 w4 = *(const float4*)(sw1 + k * 128 + 4 * l);
            float c0 = __shfl_sync(0xffffffffu, ea00, k);
            float c1 = __shfl_sync(0xffffffffu, ea10, k);
            h0.x = fmaf(c0, w4.x, h0.x); h0.y = fmaf(c0, w4.y, h0.y);
            h0.z = fmaf(c0, w4.z, h0.z); h0.w = fmaf(c0, w4.w, h0.w);
            h1.x = fmaf(c1, w4.x, h1.x); h1.y = fmaf(c1, w4.y, h1.y);
            h1.z = fmaf(c1, w4.z, h1.z); h1.w = fmaf(c1, w4.w, h1.w);
        }
#pragma unroll 8
        for (int k = 0; k < 32; k++) {
            float4 w4 = *(const float4*)(sw1 + (k + 32) * 128 + 4 * l);
            float c0 = __shfl_sync(0xffffffffu, ea01, k);
            float c1 = __shfl_sync(0xffffffffu, ea11, k);
            h0.x = fmaf(c0, w4.x, h0.x); h0.y = fmaf(c0, w4.y, h0.y);
            h0.z = fmaf(c0, w4.z, h0.z); h0.w = fmaf(c0, w4.w, h0.w);
            h1.x = fmaf(c1, w4.x, h1.x); h1.y = fmaf(c1, w4.y, h1.y);
            h1.z = fmaf(c1, w4.z, h1.z); h1.w = fmaf(c1, w4.w, h1.w);
        }
        h0.x = fmaxf(h0.x, 0.f); h0.y = fmaxf(h0.y, 0.f); h0.z = fmaxf(h0.z, 0.f); h0.w = fmaxf(h0.w, 0.f);
        h1.x = fmaxf(h1.x, 0.f); h1.y = fmaxf(h1.y, 0.f); h1.z = fmaxf(h1.z, 0.f); h1.w = fmaxf(h1.w, 0.f);
        // msg = h @ W2 + b2 (lane l owns channels 2l, 2l+1)
        float m00 = sps[192 + 2 * l], m01 = sps[192 + 2 * l + 1];
        float m10 = m00, m11 = m01;
#pragma unroll 8
        for (int kk = 0; kk < 32; kk++) {
#pragma unroll
            for (int j = 0; j < 4; j++) {
                float a0 = (j == 0) ? h0.x : (j == 1) ? h0.y : (j == 2) ? h0.z : h0.w;
                float a1 = (j == 0) ? h1.x : (j == 1) ? h1.y : (j == 2) ? h1.z : h1.w;
                float v0 = __shfl_sync(0xffffffffu, a0, kk);
                float v1 = __shfl_sync(0xffffffffu, a1, kk);
                float2 wv = *(const float2*)(sw2 + (kk * 4 + j) * 64 + 2 * l);
                m00 = fmaf(v0, wv.x, m00); m01 = fmaf(v0, wv.y, m01);
                m10 = fmaf(v1, wv.x, m10); m11 = fmaf(v1, wv.y, m11);
            }
        }
        // softmax partials: e = exp(msg*t) (no max-shift needed: |msg| small, fp32 safe)
        float e00 = __expf(m00 * t), e01 = __expf(m01 * t);
        float e10 = __expf(m10 * t), e11 = __expf(m11 * t);
        float* q0 = g_nd0 + (size_t)d0 * 128 + 4 * l;
        atomicAdd(q0,     m00 * e00); atomicAdd(q0 + 1, e00);
        atomicAdd(q0 + 2, m01 * e01); atomicAdd(q0 + 3, e01);
        float* q1 = g_nd0 + (size_t)d1 * 128 + 4 * l;
        atomicAdd(q1,     m10 * e10); atomicAdd(q1 + 1, e10);
        atomicAdd(q1 + 2, m11 * e11); atomicAdd(q1 + 3, e11);
        // raw messages become conv1's edge features
        *(float2*)(g_msg0 + (size_t)e0 * 64 + 2 * l) = make_float2(m00, m01);
        *(float2*)(g_msg0 + (size_t)e1 * 64 + 2 * l) = make_float2(m10, m11);
    }
}

// ---------------- conv1 edge pass (edge feats = LN(msg0), no msg store) ----------------
__global__ void __launch_bounds__(256) k_edge1(
    const int* __restrict__ ei,
    const float* __restrict__ eg, const float* __restrict__ eb,
    const float* __restrict__ w1, const float* __restrict__ w2,
    const float* __restrict__ b2, const float* __restrict__ tptr)
{
    extern __shared__ float sm[];
    float* sw1 = sm;                 // 8192
    float* sw2 = sm + 8192;          // 8192
    float* sps = sw2 + 8192;         // eg(64) eb(64) b2(64)
    for (int i = threadIdx.x; i < 8192; i += blockDim.x) {
        sw1[i] = w1[128 * 128 + i];
        sw2[i] = w2[i];
    }
    if (threadIdx.x < 64) {
        sps[threadIdx.x]       = eg[threadIdx.x];
        sps[64 + threadIdx.x]  = eb[threadIdx.x];
        sps[128 + threadIdx.x] = b2[threadIdx.x];
    }
    __syncthreads();
    float t = tptr[0];
    int l = threadIdx.x & 31;
    int warp = (blockIdx.x * blockDim.x + threadIdx.x) >> 5;
    int nwarps = (gridDim.x * blockDim.x) >> 5;
    const int* src = ei;
    const int* dst = ei + NE;

    for (int p = warp; p < NE / 2; p += nwarps) {
        int e0 = 2 * p, e1 = 2 * p + 1;
        int s0 = src[e0], d0 = dst[e0], s1 = src[e1], d1 = dst[e1];
        float4 pa0 = *(const float4*)(g_Pa + (size_t)d0 * 128 + 4 * l);
        float4 pb0 = *(const float4*)(g_Pb + (size_t)s0 * 128 + 4 * l);
        float4 pa1 = *(const float4*)(g_Pa + (size_t)d1 * 128 + 4 * l);
        float4 pb1 = *(const float4*)(g_Pb + (size_t)s1 * 128 + 4 * l);
        float z00 = g_msg0[(size_t)e0 * 64 + l];
        float z01 = g_msg0[(size_t)e0 * 64 + 32 + l];
        float z10 = g_msg0[(size_t)e1 * 64 + l];
        float z11 = g_msg0[(size_t)e1 * 64 + 32 + l];
        float mu0 = wsum(z00 + z01) * (1.f / 64.f);
        float sq0 = wsum(z00 * z00 + z01 * z01) * (1.f / 64.f);
        float rs0 = rsqrtf(sq0 - mu0 * mu0 + 1e-5f);
        float ea00 = (z00 - mu0) * rs0 * sps[l] + sps[64 + l];
        float ea01 = (z01 - mu0) * rs0 * sps[l + 32] + sps[64 + l + 32];
        float mu1 = wsum(z10 + z11) * (1.f / 64.f);
        float sq1 = wsum(z10 * z10 + z11 * z11) * (1.f / 64.f);
        float rs1 = rsqrtf(sq1 - mu1 * mu1 + 1e-5f);
        float ea10 = (z10 - mu1) * rs1 * sps[l] + sps[64 + l];
        float ea11 = (z11 - mu1) * rs1 * sps[l + 32] + sps[64 + l + 32];
        float4 h0, h1;
        h0.x = pa0.x + pb0.x; h0.y = pa0.y + pb0.y; h0.z = pa0.z + pb0.z; h0.w = pa0.w + pb0.w;
        h1.x = pa1.x + pb1.x; h1.y = pa1.y + pb1.y; h1.z = pa1.z + pb1.z; h1.w = pa1.w + pb1.w;
#pragma unroll 8
        for (int k = 0; k < 32; k++) {
            float4 w4 = *(const float4*)(sw1 + k * 128 + 4 * l);
            float c0 = __shfl_sync(0xffffffffu, ea00, k);
            float c1 = __shfl_sync(0xffffffffu, ea10, k);
            h0.x = fmaf(c0, w4.x, h0.x); h0.y = fmaf(c0, w4.y, h0.y);
            h0.z = fmaf(c0, w4.z, h0.z); h0.w = fmaf(c0, w4.w, h0.w);
            h1.x = fmaf(c1, w4.x, h1.x); h1.y = fmaf(c1, w4.y, h1.y);
            h1.z = fmaf(c1, w4.z, h1.z); h1.w = fmaf(c1, w4.w, h1.w);
        }
#pragma unroll 8
        for (int k = 0; k < 32; k++) {
            float4 w4 = *(const float4*)(sw1 + (k + 32) * 128 + 4 * l);
            float c0 = __shfl_sync(0xffffffffu, ea01, k);
            float c1 = __shfl_sync(0xffffffffu, ea11, k);
            h0.x = fmaf(c0, w4.x, h0.x); h0.y = fmaf(c0, w4.y, h0.y);
            h0.z = fmaf(c0, w4.z, h0.z); h0.w = fmaf(c0, w4.w, h0.w);
            h1.x = fmaf(c1, w4.x, h1.x); h1.y = fmaf(c1, w4.y, h1.y);
            h1.z = fmaf(c1, w4.z, h1.z); h1.w = fmaf(c1, w4.w, h1.w);
        }
        h0.x = fmaxf(h0.x, 0.f); h0.y = fmaxf(h0.y, 0.f); h0.z = fmaxf(h0.z, 0.f); h0.w = fmaxf(h0.w, 0.f);
        h1.x = fmaxf(h1.x, 0.f); h1.y = fmaxf(h1.y, 0.f); h1.z = fmaxf(h1.z, 0.f); h1.w = fmaxf(h1.w, 0.f);
        float m00 = sps[128 + 2 * l], m01 = sps[128 + 2 * l + 1];
        float m10 = m00, m11 = m01;
#pragma unroll 8
        for (int kk = 0; kk < 32; kk++) {
#pragma unroll
            for (int j = 0; j < 4; j++) {
                float a0 = (j == 0) ? h0.x : (j == 1) ? h0.y : (j == 2) ? h0.z : h0.w;
                float a1 = (j == 0) ? h1.x : (j == 1) ? h1.y : (j == 2) ? h1.z : h1.w;
                float v0 = __shfl_sync(0xffffffffu, a0, kk);
                float v1 = __shfl_sync(0xffffffffu, a1, kk);
                float2 wv = *(const float2*)(sw2 + (kk * 4 + j) * 64 + 2 * l);
                m00 = fmaf(v0, wv.x, m00); m01 = fmaf(v0, wv.y, m01);
                m10 = fmaf(v1, wv.x, m10); m11 = fmaf(v1, wv.y, m11);
            }
        }
        float e00 = __expf(m00 * t), e01 = __expf(m01 * t);
        float e10 = __expf(m10 * t), e11 = __expf(m11 * t);
        float* q0 = g_nd1 + (size_t)d0 * 128 + 4 * l;
        atomicAdd(q0,     m00 * e00); atomicAdd(q0 + 1, e00);
        atomicAdd(q0 + 2, m01 * e01); atomicAdd(q0 + 3, e01);
        float* q1 = g_nd1 + (size_t)d1 * 128 + 4 * l;
        atomicAdd(q1,     m10 * e10); atomicAdd(q1 + 1, e10);
        atomicAdd(q1 + 2, m11 * e11); atomicAdd(q1 + 3, e11);
    }
}

// ---------------- conv0 node finish: x1 = num/den + xenc@wr ; h1 = relu(LN(x1)) ----------------
__global__ void __launch_bounds__(256) k_node0(
    const float* __restrict__ wr, const float* __restrict__ lg, const float* __restrict__ lb)
{
    extern __shared__ float sm[];            // wr 64*64
    for (int i = threadIdx.x; i < 64 * 64; i += blockDim.x) sm[i] = wr[i];
    __syncthreads();
    int l = threadIdx.x & 31;
    int warp = (blockIdx.x * blockDim.x + threadIdx.x) >> 5;
    int nwarps = (gridDim.x * blockDim.x) >> 5;
    float g0 = lg[l], g1 = lg[l + 32], b0 = lb[l], b1v = lb[l + 32];
    for (int n = warp; n < NN; n += nwarps) {
        float xe0 = g_xenc[n * 64 + l], xe1 = g_xenc[n * 64 + 32 + l];
        float r0 = 0.f, r1 = 0.f;
#pragma unroll 8
        for (int k = 0; k < 32; k++) {
            float xk = __shfl_sync(0xffffffffu, xe0, k);
            r0 = fmaf(xk, sm[k * 64 + l], r0);
            r1 = fmaf(xk, sm[k * 64 + l + 32], r1);
        }
#pragma unroll 8
        for (int k = 0; k < 32; k++) {
            float xk = __shfl_sync(0xffffffffu, xe1, k);
            r0 = fmaf(xk, sm[(k + 32) * 64 + l], r0);
            r1 = fmaf(xk, sm[(k + 32) * 64 + l + 32], r1);
        }
        float2 na = *(const float2*)(g_nd0 + (size_t)n * 128 + 2 * l);
        float2 nb = *(const float2*)(g_nd0 + (size_t)n * 128 + 64 + 2 * l);
        float x10 = ((na.y != 0.f) ? na.x / na.y : 0.f) + r0;
        float x11 = ((nb.y != 0.f) ? nb.x / nb.y : 0.f) + r1;
        g_x1[n * 64 + l] = x10;
        g_x1[n * 64 + l + 32] = x11;
        float mu = wsum(x10 + x11) * (1.f / 64.f);
        float sq = wsum(x10 * x10 + x11 * x11) * (1.f / 64.f);
        float rs = rsqrtf(sq - mu * mu + 1e-5f);
        g_h1[n * 64 + l]      = fmaxf((x10 - mu) * rs * g0 + b0, 0.f);
        g_h1[n * 64 + l + 32] = fmaxf((x11 - mu) * rs * g1 + b1v, 0.f);
    }
}

// ---------------- final: out = x1 + num1/den1 + h1@c1_wr ----------------
__global__ void __launch_bounds__(256) k_node1(
    const float* __restrict__ wr, float* __restrict__ out)
{
    extern __shared__ float sm[];            // wr 64*64
    for (int i = threadIdx.x; i < 64 * 64; i += blockDim.x) sm[i] = wr[i];
    __syncthreads();
    int l = threadIdx.x & 31;
    int warp = (blockIdx.x * blockDim.x + threadIdx.x) >> 5;
    int nwarps = (gridDim.x * blockDim.x) >> 5;
    for (int n = warp; n < NN; n += nwarps) {
        float he0 = g_h1[n * 64 + l], he1 = g_h1[n * 64 + 32 + l];
        float r0 = 0.f, r1 = 0.f;
#pragma unroll 8
        for (int k = 0; k < 32; k++) {
            float xk = __shfl_sync(0xffffffffu, he0, k);
            r0 = fmaf(xk, sm[k * 64 + l], r0);
            r1 = fmaf(xk, sm[k * 64 + l + 32], r1);
        }
#pragma unroll 8
        for (int k = 0; k < 32; k++) {
            float xk = __shfl_sync(0xffffffffu, he1, k);
            r0 = fmaf(xk, sm[(k + 32) * 64 + l], r0);
            r1 = fmaf(xk, sm[(k + 32) * 64 + l + 32], r1);
        }
        float2 na = *(const float2*)(g_nd1 + (size_t)n * 128 + 2 * l);
        float2 nb = *(const float2*)(g_nd1 + (size_t)n * 128 + 64 + 2 * l);
        float a0 = ((na.y != 0.f) ? na.x / na.y : 0.f) + r0;
        float a1 = ((nb.y != 0.f) ? nb.x / nb.y : 0.f) + r1;
        out[n * 64 + l]      = g_x1[n * 64 + l] + a0;
        out[n * 64 + l + 32] = g_x1[n * 64 + l + 32] + a1;
    }
}

extern "C" void kernel_launch(void* const* d_in, const int* in_sizes, int n_in,
                              void* d_out, int out_size)
{
    const float* x       = (const float*)d_in[0];
    const int*   ei      = (const int*)  d_in[1];
    const float* eattr   = (const float*)d_in[2];
    const float* enc_w   = (const float*)d_in[3];
    const float* enc_b   = (const float*)d_in[4];
    const float* enc_g   = (const float*)d_in[5];
    const float* enc_bb  = (const float*)d_in[6];
    const float* eenc_w  = (const float*)d_in[7];
    const float* eenc_b  = (const float*)d_in[8];
    const float* eenc_g  = (const float*)d_in[9];
    const float* eenc_bb = (const float*)d_in[10];
    const float* c0_w1   = (const float*)d_in[11];
    const float* c0_b1   = (const float*)d_in[12];
    const float* c0_w2   = (const float*)d_in[13];
    const float* c0_b2   = (const float*)d_in[14];
    const float* c0_wr   = (const float*)d_in[15];
    const float* c0_t    = (const float*)d_in[16];
    const float* l1_g    = (const float*)d_in[17];
    const float* l1_b    = (const float*)d_in[18];
    const float* l1_eg   = (const float*)d_in[19];
    const float* l1_eb   = (const float*)d_in[20];
    const float* c1_w1   = (const float*)d_in[21];
    const float* c1_b1   = (const float*)d_in[22];
    const float* c1_w2   = (const float*)d_in[23];
    const float* c1_b2   = (const float*)d_in[24];
    const float* c1_wr   = (const float*)d_in[25];
    const float* c1_t    = (const float*)d_in[26];
    float* out = (float*)d_out;

    cudaFuncSetAttribute(k_prep,  cudaFuncAttributeMaxDynamicSharedMemorySize, 65536);
    cudaFuncSetAttribute(k_edge0, cudaFuncAttributeMaxDynamicSharedMemorySize, 70656);
    cudaFuncSetAttribute(k_edge1, cudaFuncAttributeMaxDynamicSharedMemorySize, 66304);

    k_zero<<<2500, 256>>>();
    k_encode<<<320, 256, 24576>>>(x, enc_w, enc_b, enc_g, enc_bb);
    k_prep<<<444, 256, 65536>>>(0, c0_w1, c0_b1);
    k_edge0<<<592, 256, 70656>>>(ei, eattr, eenc_w, eenc_b, eenc_g, eenc_bb,
                                 c0_w1, c0_w2, c0_b2, c0_t);
    k_node0<<<320, 256, 16384>>>(c0_wr, l1_g, l1_b);
    k_prep<<<444, 256, 65536>>>(1, c1_w1, c1_b1);
    k_edge1<<<592, 256, 66304>>>(ei, l1_eg, l1_eb, c1_w1, c1_w2, c1_b2, c1_t);
    k_node1<<<320, 256, 16384>>>(c1_wr, out);
}

// round 2
// speedup vs baseline: 1.2483x; 1.2483x over previous
#include <cuda_runtime.h>
#include <math.h>

#define NN 20000
#define NE 640000

typedef unsigned long long u64;

// ---------------- scratch (device globals; no allocation at runtime) ----------------
__device__ __align__(16) float g_xenc[NN * 64];   // encoded nodes
__device__ __align__(16) float g_x1[NN * 64];     // conv0 output (pre-res+ LN)
__device__ __align__(16) float g_h1[NN * 64];     // relu(LN(x1)) = conv1 node input
__device__ __align__(16) float g_Pa[NN * 128];    // per-node dst-part of W1 (+b1)
__device__ __align__(16) float g_Pb[NN * 128];    // per-node src-part of W1
__device__ __align__(16) float g_nd0[NN * 128];   // conv0 (num,den) interleaved per channel
__device__ __align__(16) float g_nd1[NN * 128];   // conv1 (num,den)
__device__ __align__(16) float g_msg0[(size_t)NE * 64]; // conv0 raw messages

// ---------------- f32x2 packed helpers ----------------
static __device__ __forceinline__ u64 fma2(u64 a, u64 b, u64 c) {
    u64 d; asm("fma.rn.f32x2 %0,%1,%2,%3;" : "=l"(d) : "l"(a), "l"(b), "l"(c)); return d;
}
static __device__ __forceinline__ u64 add2(u64 a, u64 b) {
    u64 d; asm("add.rn.f32x2 %0,%1,%2;" : "=l"(d) : "l"(a), "l"(b)); return d;
}
static __device__ __forceinline__ u64 mul2(u64 a, u64 b) {
    u64 d; asm("mul.rn.f32x2 %0,%1,%2;" : "=l"(d) : "l"(a), "l"(b)); return d;
}
static __device__ __forceinline__ u64 pack2(float lo, float hi) {
    u64 d; asm("mov.b64 %0,{%1,%2};" : "=l"(d) : "f"(lo), "f"(hi)); return d;
}
static __device__ __forceinline__ void unpack2(u64 a, float& lo, float& hi) {
    asm("mov.b64 {%0,%1},%2;" : "=f"(lo), "=f"(hi) : "l"(a));
}

static __device__ __forceinline__ float wsum(float v) {
#pragma unroll
    for (int o = 16; o; o >>= 1) v += __shfl_xor_sync(0xffffffffu, v, o);
    return v;
}

// ---------------- zero num/den accumulators ----------------
__global__ void k_zero() {
    int i = blockIdx.x * blockDim.x + threadIdx.x;
    if (i < NN * 128 / 4) {
        float4 z = make_float4(0.f, 0.f, 0.f, 0.f);
        ((float4*)g_nd0)[i] = z;
        ((float4*)g_nd1)[i] = z;
    }
}

// ---------------- node encoder: x_enc = LN(x @ enc_w + enc_b) ----------------
__global__ void __launch_bounds__(256) k_encode(
    const float* __restrict__ x, const float* __restrict__ enc_w,
    const float* __restrict__ enc_b, const float* __restrict__ enc_g,
    const float* __restrict__ enc_bb)
{
    extern __shared__ float sm[];            // enc_w: 96*64
    for (int i = threadIdx.x; i < 96 * 64; i += blockDim.x) sm[i] = enc_w[i];
    __syncthreads();
    int l = threadIdx.x & 31;
    int warp = (blockIdx.x * blockDim.x + threadIdx.x) >> 5;
    int nwarps = (gridDim.x * blockDim.x) >> 5;
    float b0 = enc_b[l], b1v = enc_b[l + 32];
    float g0 = enc_g[l], g1 = enc_g[l + 32];
    float bb0 = enc_bb[l], bb1 = enc_bb[l + 32];
    for (int n = warp; n < NN; n += nwarps) {
        float xa = x[(size_t)n * 96 + l];
        float xb = x[(size_t)n * 96 + 32 + l];
        float xc = x[(size_t)n * 96 + 64 + l];
        float z0 = b0, z1 = b1v;
#pragma unroll 8
        for (int k = 0; k < 32; k++) {
            float xk = __shfl_sync(0xffffffffu, xa, k);
            z0 = fmaf(xk, sm[k * 64 + l], z0);
            z1 = fmaf(xk, sm[k * 64 + l + 32], z1);
        }
#pragma unroll 8
        for (int k = 0; k < 32; k++) {
            float xk = __shfl_sync(0xffffffffu, xb, k);
            z0 = fmaf(xk, sm[(k + 32) * 64 + l], z0);
            z1 = fmaf(xk, sm[(k + 32) * 64 + l + 32], z1);
        }
#pragma unroll 8
        for (int k = 0; k < 32; k++) {
            float xk = __shfl_sync(0xffffffffu, xc, k);
            z0 = fmaf(xk, sm[(k + 64) * 64 + l], z0);
            z1 = fmaf(xk, sm[(k + 64) * 64 + l + 32], z1);
        }
        float mu = wsum(z0 + z1) * (1.f / 64.f);
        float sq = wsum(z0 * z0 + z1 * z1) * (1.f / 64.f);
        float rs = rsqrtf(sq - mu * mu + 1e-5f);
        g_xenc[n * 64 + l]      = (z0 - mu) * rs * g0 + bb0;
        g_xenc[n * 64 + l + 32] = (z1 - mu) * rs * g1 + bb1;
    }
}

// ---------------- Pa = xin @ W1[0:64] + b1 ; Pb = xin @ W1[64:128] ----------------
__global__ void __launch_bounds__(256) k_prep(
    int use_h, const float* __restrict__ w1, const float* __restrict__ b1)
{
    extern __shared__ float sm[];            // w1 rows 0..127: 128*128
    for (int i = threadIdx.x; i < 128 * 128; i += blockDim.x) sm[i] = w1[i];
    __syncthreads();
    const float* xin = use_h ? g_h1 : g_xenc;
    int l = threadIdx.x & 31;
    int warp = (blockIdx.x * blockDim.x + threadIdx.x) >> 5;
    int nwarps = (gridDim.x * blockDim.x) >> 5;
    float4 bv = *(const float4*)(b1 + 4 * l);
    for (int n = warp; n < NN; n += nwarps) {
        float x0 = xin[n * 64 + l], x1 = xin[n * 64 + 32 + l];
        float4 pa = bv;
        float4 pb = make_float4(0.f, 0.f, 0.f, 0.f);
#pragma unroll 8
        for (int k = 0; k < 32; k++) {
            float xk = __shfl_sync(0xffffffffu, x0, k);
            float4 wa = *(const float4*)(sm + k * 128 + 4 * l);
            float4 wb = *(const float4*)(sm + (k + 64) * 128 + 4 * l);
            pa.x = fmaf(xk, wa.x, pa.x); pa.y = fmaf(xk, wa.y, pa.y);
            pa.z = fmaf(xk, wa.z, pa.z); pa.w = fmaf(xk, wa.w, pa.w);
            pb.x = fmaf(xk, wb.x, pb.x); pb.y = fmaf(xk, wb.y, pb.y);
            pb.z = fmaf(xk, wb.z, pb.z); pb.w = fmaf(xk, wb.w, pb.w);
        }
#pragma unroll 8
        for (int k = 0; k < 32; k++) {
            float xk = __shfl_sync(0xffffffffu, x1, k);
            float4 wa = *(const float4*)(sm + (k + 32) * 128 + 4 * l);
            float4 wb = *(const float4*)(sm + (k + 96) * 128 + 4 * l);
            pa.x = fmaf(xk, wa.x, pa.x); pa.y = fmaf(xk, wa.y, pa.y);
            pa.z = fmaf(xk, wa.z, pa.z); pa.w = fmaf(xk, wa.w, pa.w);
            pb.x = fmaf(xk, wb.x, pb.x); pb.y = fmaf(xk, wb.y, pb.y);
            pb.z = fmaf(xk, wb.z, pb.z); pb.w = fmaf(xk, wb.w, pb.w);
        }
        *(float4*)(g_Pa + (size_t)n * 128 + 4 * l) = pa;
        *(float4*)(g_Pb + (size_t)n * 128 + 4 * l) = pb;
    }
}

// ---------------- conv0 edge pass: thread-per-edge, f32x2, zero shfl ----------------
// smem layout (bytes):
//   [0, 32768)      sw1p : float2[32][128]  packed k-pairs of W1 rows 128..191
//   [32768, 65536)  sw2  : float [128][64]  W2 (channel pairs read in-place)
//   [65536, 69632)  sep  : float2[8][64]    packed k-pairs of eenc_w
//   [69632, 70656)  seb, sg, sbb, sb2 : float2[32] each
__global__ void __launch_bounds__(128) k_edge0(
    const int* __restrict__ ei, const float* __restrict__ eattr,
    const float* __restrict__ eenc_w, const float* __restrict__ eenc_b,
    const float* __restrict__ eenc_g, const float* __restrict__ eenc_bb,
    const float* __restrict__ w1, const float* __restrict__ w2,
    const float* __restrict__ b2, const float* __restrict__ tptr)
{
    extern __shared__ __align__(16) char smraw[];
    float2* sw1p = (float2*)smraw;
    float*  sw2  = (float*)(smraw + 32768);
    float2* sep  = (float2*)(smraw + 65536);
    float2* seb  = (float2*)(smraw + 69632);
    float2* sg   = (float2*)(smraw + 69888);
    float2* sbb  = (float2*)(smraw + 70144);
    float2* sb2  = (float2*)(smraw + 70400);
    int tid = threadIdx.x;
    for (int i = tid; i < 4096; i += 128) {
        int k2 = i >> 7, c = i & 127;
        sw1p[i] = make_float2(w1[(128 + 2 * k2) * 128 + c], w1[(129 + 2 * k2) * 128 + c]);
    }
    for (int i = tid; i < 8192; i += 128) sw2[i] = w2[i];
    for (int i = tid; i < 512; i += 128) {
        int k2 = i >> 6, c = i & 63;
        sep[i] = make_float2(eenc_w[(2 * k2) * 64 + c], eenc_w[(2 * k2 + 1) * 64 + c]);
    }
    if (tid < 32) {
        seb[tid] = ((const float2*)eenc_b)[tid];
        sg[tid]  = ((const float2*)eenc_g)[tid];
        sbb[tid] = ((const float2*)eenc_bb)[tid];
        sb2[tid] = ((const float2*)b2)[tid];
    }
    __syncthreads();
    float t = tptr[0];
    const int* src = ei;
    const int* dst = ei + NE;
    int stride = gridDim.x * blockDim.x;

    for (int e = blockIdx.x * blockDim.x + tid; e < NE; e += stride) {
        int s = src[e], d = dst[e];
        // ---- edge attr: 16 floats = 8 natural k-pairs ----
        u64 ap[8];
        {
            const ulonglong2* ev = (const ulonglong2*)(eattr + (size_t)e * 16);
            ulonglong2 t0 = ev[0], t1 = ev[1], t2 = ev[2], t3 = ev[3];
            ap[0] = t0.x; ap[1] = t0.y; ap[2] = t1.x; ap[3] = t1.y;
            ap[4] = t2.x; ap[5] = t2.y; ap[6] = t3.x; ap[7] = t3.y;
        }
        // ---- edge encoder linear (k-split packed accumulation) ----
        u64 z[32];
#pragma unroll
        for (int half = 0; half < 2; half++) {
            u64 acc[32];
#pragma unroll
            for (int c = 0; c < 32; c++) acc[c] = 0ull;
#pragma unroll
            for (int k2 = 0; k2 < 8; k2++) {
                const ulonglong2* wv = (const ulonglong2*)(sep + k2 * 64 + half * 32);
                u64 a = ap[k2];
#pragma unroll
                for (int c2 = 0; c2 < 16; c2++) {
                    ulonglong2 w = wv[c2];
                    acc[2 * c2]     = fma2(a, w.x, acc[2 * c2]);
                    acc[2 * c2 + 1] = fma2(a, w.y, acc[2 * c2 + 1]);
                }
            }
#pragma unroll
            for (int q = 0; q < 16; q++) {
                float l0, h0, l1, h1;
                unpack2(acc[2 * q], l0, h0); unpack2(acc[2 * q + 1], l1, h1);
                z[half * 16 + q] = add2(pack2(l0 + h0, l1 + h1), *(const u64*)(seb + half * 16 + q));
            }
        }
        // ---- in-thread LayerNorm ----
        u64 s2 = 0ull, q2 = 0ull;
#pragma unroll
        for (int p = 0; p < 32; p++) { s2 = add2(s2, z[p]); q2 = fma2(z[p], z[p], q2); }
        float sl, sh, ql, qh; unpack2(s2, sl, sh); unpack2(q2, ql, qh);
        float mu = (sl + sh) * (1.f / 64.f), msq = (ql + qh) * (1.f / 64.f);
        float rs = rsqrtf(msq - mu * mu + 1e-5f);
        u64 nmu2 = pack2(-mu, -mu), rs2 = pack2(rs, rs);
        u64 ea[32];
#pragma unroll
        for (int p = 0; p < 32; p++) {
            u64 cen = mul2(add2(z[p], nmu2), rs2);
            ea[p] = fma2(cen, *(const u64*)(sg + p), *(const u64*)(sbb + p));
        }
        // ---- main MLP: h = relu(Pa[d]+Pb[s]+ea@W1c), msg = h@W2+b2, fused ----
        u64 macc[32];
#pragma unroll
        for (int p = 0; p < 32; p++) macc[p] = *(const u64*)(sb2 + p);
        const float4* pav = (const float4*)(g_Pa + (size_t)d * 128);
        const float4* pbv = (const float4*)(g_Pb + (size_t)s * 128);
#pragma unroll 1
        for (int ch = 0; ch < 8; ch++) {
            u64 ha[16];
#pragma unroll
            for (int j4 = 0; j4 < 4; j4++) {
                float4 a = pav[ch * 4 + j4];
                float4 b = pbv[ch * 4 + j4];
                ha[4 * j4 + 0] = pack2(a.x + b.x, 0.f);
                ha[4 * j4 + 1] = pack2(a.y + b.y, 0.f);
                ha[4 * j4 + 2] = pack2(a.z + b.z, 0.f);
                ha[4 * j4 + 3] = pack2(a.w + b.w, 0.f);
            }
#pragma unroll
            for (int k2 = 0; k2 < 32; k2++) {
                const ulonglong2* wv = (const ulonglong2*)(sw1p + k2 * 128 + ch * 16);
                u64 ek = ea[k2];
#pragma unroll
                for (int c2 = 0; c2 < 8; c2++) {
                    ulonglong2 w = wv[c2];
                    ha[2 * c2]     = fma2(ek, w.x, ha[2 * c2]);
                    ha[2 * c2 + 1] = fma2(ek, w.y, ha[2 * c2 + 1]);
                }
            }
#pragma unroll
            for (int k = 0; k < 16; k++) {
                float lo, hi; unpack2(ha[k], lo, hi);
                float hv = fmaxf(lo + hi, 0.f);
                u64 hd = pack2(hv, hv);
                const ulonglong2* wv = (const ulonglong2*)sw2 + (ch * 16 + k) * 16;
#pragma unroll
                for (int c4 = 0; c4 < 16; c4++) {
                    ulonglong2 w = wv[c4];
                    macc[2 * c4]     = fma2(hd, w.x, macc[2 * c4]);
                    macc[2 * c4 + 1] = fma2(hd, w.y, macc[2 * c4 + 1]);
                }
            }
        }
        // ---- epilogue: exp, packed red, msg store ----
        float* nd = g_nd0 + (size_t)d * 128;
#pragma unroll
        for (int p = 0; p < 32; p++) {
            float m0, m1; unpack2(macc[p], m0, m1);
            float e0 = __expf(m0 * t), e1 = __expf(m1 * t);
            asm volatile("red.global.add.v4.f32 [%0], {%1,%2,%3,%4};"
                         :: "l"(nd + 4 * p), "f"(m0 * e0), "f"(e0), "f"(m1 * e1), "f"(e1)
                         : "memory");
        }
        ulonglong2* ms = (ulonglong2*)(g_msg0 + (size_t)e * 64);
#pragma unroll
        for (int q = 0; q < 16; q++) {
            ulonglong2 v; v.x = macc[2 * q]; v.y = macc[2 * q + 1];
            ms[q] = v;
        }
    }
}

// ---------------- conv1 edge pass: edge feat = LN(msg0), no msg store ----------------
__global__ void __launch_bounds__(128) k_edge1(
    const int* __restrict__ ei,
    const float* __restrict__ eg, const float* __restrict__ eb,
    const float* __restrict__ w1, const float* __restrict__ w2,
    const float* __restrict__ b2, const float* __restrict__ tptr)
{
    extern __shared__ __align__(16) char smraw[];
    float2* sw1p = (float2*)smraw;
    float*  sw2  = (float*)(smraw + 32768);
    float2* sg   = (float2*)(smraw + 65536);
    float2* sbb  = (float2*)(smraw + 65792);
    float2* sb2  = (float2*)(smraw + 66048);
    int tid = threadIdx.x;
    for (int i = tid; i < 4096; i += 128) {
        int k2 = i >> 7, c = i & 127;
        sw1p[i] = make_float2(w1[(128 + 2 * k2) * 128 + c], w1[(129 + 2 * k2) * 128 + c]);
    }
    for (int i = tid; i < 8192; i += 128) sw2[i] = w2[i];
    if (tid < 32) {
        sg[tid]  = ((const float2*)eg)[tid];
        sbb[tid] = ((const float2*)eb)[tid];
        sb2[tid] = ((const float2*)b2)[tid];
    }
    __syncthreads();
    float t = tptr[0];
    const int* src = ei;
    const int* dst = ei + NE;
    int stride = gridDim.x * blockDim.x;

    for (int e = blockIdx.x * blockDim.x + tid; e < NE; e += stride) {
        int s = src[e], d = dst[e];
        // ---- load msg0 as packed pairs ----
        u64 z[32];
        {
            const ulonglong2* mv = (const ulonglong2*)(g_msg0 + (size_t)e * 64);
#pragma unroll
            for (int q = 0; q < 16; q++) {
                ulonglong2 v = mv[q];
                z[2 * q] = v.x; z[2 * q + 1] = v.y;
            }
        }
        // ---- LN ----
        u64 s2 = 0ull, q2 = 0ull;
#pragma unroll
        for (int p = 0; p < 32; p++) { s2 = add2(s2, z[p]); q2 = fma2(z[p], z[p], q2); }
        float sl, sh, ql, qh; unpack2(s2, sl, sh); unpack2(q2, ql, qh);
        float mu = (sl + sh) * (1.f / 64.f), msq = (ql + qh) * (1.f / 64.f);
        float rs = rsqrtf(msq - mu * mu + 1e-5f);
        u64 nmu2 = pack2(-mu, -mu), rs2 = pack2(rs, rs);
        u64 ea[32];
#pragma unroll
        for (int p = 0; p < 32; p++) {
            u64 cen = mul2(add2(z[p], nmu2), rs2);
            ea[p] = fma2(cen, *(const u64*)(sg + p), *(const u64*)(sbb + p));
        }
        // ---- main MLP ----
        u64 macc[32];
#pragma unroll
        for (int p = 0; p < 32; p++) macc[p] = *(const u64*)(sb2 + p);
        const float4* pav = (const float4*)(g_Pa + (size_t)d * 128);
        const float4* pbv = (const float4*)(g_Pb + (size_t)s * 128);
#pragma unroll 1
        for (int ch = 0; ch < 8; ch++) {
            u64 ha[16];
#pragma unroll
            for (int j4 = 0; j4 < 4; j4++) {
                float4 a = pav[ch * 4 + j4];
                float4 b = pbv[ch * 4 + j4];
                ha[4 * j4 + 0] = pack2(a.x + b.x, 0.f);
                ha[4 * j4 + 1] = pack2(a.y + b.y, 0.f);
                ha[4 * j4 + 2] = pack2(a.z + b.z, 0.f);
                ha[4 * j4 + 3] = pack2(a.w + b.w, 0.f);
            }
#pragma unroll
            for (int k2 = 0; k2 < 32; k2++) {
                const ulonglong2* wv = (const ulonglong2*)(sw1p + k2 * 128 + ch * 16);
                u64 ek = ea[k2];
#pragma unroll
                for (int c2 = 0; c2 < 8; c2++) {
                    ulonglong2 w = wv[c2];
                    ha[2 * c2]     = fma2(ek, w.x, ha[2 * c2]);
                    ha[2 * c2 + 1] = fma2(ek, w.y, ha[2 * c2 + 1]);
                }
            }
#pragma unroll
            for (int k = 0; k < 16; k++) {
                float lo, hi; unpack2(ha[k], lo, hi);
                float hv = fmaxf(lo + hi, 0.f);
                u64 hd = pack2(hv, hv);
                const ulonglong2* wv = (const ulonglong2*)sw2 + (ch * 16 + k) * 16;
#pragma unroll
                for (int c4 = 0; c4 < 16; c4++) {
                    ulonglong2 w = wv[c4];
                    macc[2 * c4]     = fma2(hd, w.x, macc[2 * c4]);
                    macc[2 * c4 + 1] = fma2(hd, w.y, macc[2 * c4 + 1]);
                }
            }
        }
        // ---- epilogue ----
        float* nd = g_nd1 + (size_t)d * 128;
#pragma unroll
        for (int p = 0; p < 32; p++) {
            float m0, m1; unpack2(macc[p], m0, m1);
            float e0 = __expf(m0 * t), e1 = __expf(m1 * t);
            asm volatile("red.global.add.v4.f32 [%0], {%1,%2,%3,%4};"
                         :: "l"(nd + 4 * p), "f"(m0 * e0), "f"(e0), "f"(m1 * e1), "f"(e1)
                         : "memory");
        }
    }
}

// ---------------- conv0 node finish: x1 = num/den + xenc@wr ; h1 = relu(LN(x1)) ----------------
__global__ void __launch_bounds__(256) k_node0(
    const float* __restrict__ wr, const float* __restrict__ lg, const float* __restrict__ lb)
{
    extern __shared__ float sm[];            // wr 64*64
    for (int i = threadIdx.x; i < 64 * 64; i += blockDim.x) sm[i] = wr[i];
    __syncthreads();
    int l = threadIdx.x & 31;
    int warp = (blockIdx.x * blockDim.x + threadIdx.x) >> 5;
    int nwarps = (gridDim.x * blockDim.x) >> 5;
    float g0 = lg[l], g1 = lg[l + 32], b0 = lb[l], b1v = lb[l + 32];
    for (int n = warp; n < NN; n += nwarps) {
        float xe0 = g_xenc[n * 64 + l], xe1 = g_xenc[n * 64 + 32 + l];
        float r0 = 0.f, r1 = 0.f;
#pragma unroll 8
        for (int k = 0; k < 32; k++) {
            float xk = __shfl_sync(0xffffffffu, xe0, k);
            r0 = fmaf(xk, sm[k * 64 + l], r0);
            r1 = fmaf(xk, sm[k * 64 + l + 32], r1);
        }
#pragma unroll 8
        for (int k = 0; k < 32; k++) {
            float xk = __shfl_sync(0xffffffffu, xe1, k);
            r0 = fmaf(xk, sm[(k + 32) * 64 + l], r0);
            r1 = fmaf(xk, sm[(k + 32) * 64 + l + 32], r1);
        }
        float2 na = *(const float2*)(g_nd0 + (size_t)n * 128 + 2 * l);
        float2 nb = *(const float2*)(g_nd0 + (size_t)n * 128 + 64 + 2 * l);
        float x10 = ((na.y != 0.f) ? na.x / na.y : 0.f) + r0;
        float x11 = ((nb.y != 0.f) ? nb.x / nb.y : 0.f) + r1;
        g_x1[n * 64 + l] = x10;
        g_x1[n * 64 + l + 32] = x11;
        float mu = wsum(x10 + x11) * (1.f / 64.f);
        float sq = wsum(x10 * x10 + x11 * x11) * (1.f / 64.f);
        float rs = rsqrtf(sq - mu * mu + 1e-5f);
        g_h1[n * 64 + l]      = fmaxf((x10 - mu) * rs * g0 + b0, 0.f);
        g_h1[n * 64 + l + 32] = fmaxf((x11 - mu) * rs * g1 + b1v, 0.f);
    }
}

// ---------------- final: out = x1 + num1/den1 + h1@c1_wr ----------------
__global__ void __launch_bounds__(256) k_node1(
    const float* __restrict__ wr, float* __restrict__ out)
{
    extern __shared__ float sm[];            // wr 64*64
    for (int i = threadIdx.x; i < 64 * 64; i += blockDim.x) sm[i] = wr[i];
    __syncthreads();
    int l = threadIdx.x & 31;
    int warp = (blockIdx.x * blockDim.x + threadIdx.x) >> 5;
    int nwarps = (gridDim.x * blockDim.x) >> 5;
    for (int n = warp; n < NN; n += nwarps) {
        float he0 = g_h1[n * 64 + l], he1 = g_h1[n * 64 + 32 + l];
        float r0 = 0.f, r1 = 0.f;
#pragma unroll 8
        for (int k = 0; k < 32; k++) {
            float xk = __shfl_sync(0xffffffffu, he0, k);
            r0 = fmaf(xk, sm[k * 64 + l], r0);
            r1 = fmaf(xk, sm[k * 64 + l + 32], r1);
        }
#pragma unroll 8
        for (int k = 0; k < 32; k++) {
            float xk = __shfl_sync(0xffffffffu, he1, k);
            r0 = fmaf(xk, sm[(k + 32) * 64 + l], r0);
            r1 = fmaf(xk, sm[(k + 32) * 64 + l + 32], r1);
        }
        float2 na = *(const float2*)(g_nd1 + (size_t)n * 128 + 2 * l);
        float2 nb = *(const float2*)(g_nd1 + (size_t)n * 128 + 64 + 2 * l);
        float a0 = ((na.y != 0.f) ? na.x / na.y : 0.f) + r0;
        float a1 = ((nb.y != 0.f) ? nb.x / nb.y : 0.f) + r1;
        out[n * 64 + l]      = g_x1[n * 64 + l] + a0;
        out[n * 64 + l + 32] = g_x1[n * 64 + l + 32] + a1;
    }
}

extern "C" void kernel_launch(void* const* d_in, const int* in_sizes, int n_in,
                              void* d_out, int out_size)
{
    const float* x       = (const float*)d_in[0];
    const int*   ei      = (const int*)  d_in[1];
    const float* eattr   = (const float*)d_in[2];
    const float* enc_w   = (const float*)d_in[3];
    const float* enc_b   = (const float*)d_in[4];
    const float* enc_g   = (const float*)d_in[5];
    const float* enc_bb  = (const float*)d_in[6];
    const float* eenc_w  = (const float*)d_in[7];
    const float* eenc_b  = (const float*)d_in[8];
    const float* eenc_g  = (const float*)d_in[9];
    const float* eenc_bb = (const float*)d_in[10];
    const float* c0_w1   = (const float*)d_in[11];
    const float* c0_b1   = (const float*)d_in[12];
    const float* c0_w2   = (const float*)d_in[13];
    const float* c0_b2   = (const float*)d_in[14];
    const float* c0_wr   = (const float*)d_in[15];
    const float* c0_t    = (const float*)d_in[16];
    const float* l1_g    = (const float*)d_in[17];
    const float* l1_b    = (const float*)d_in[18];
    const float* l1_eg   = (const float*)d_in[19];
    const float* l1_eb   = (const float*)d_in[20];
    const float* c1_w1   = (const float*)d_in[21];
    const float* c1_b1   = (const float*)d_in[22];
    const float* c1_w2   = (const float*)d_in[23];
    const float* c1_b2   = (const float*)d_in[24];
    const float* c1_wr   = (const float*)d_in[25];
    const float* c1_t    = (const float*)d_in[26];
    float* out = (float*)d_out;

    cudaFuncSetAttribute(k_prep,  cudaFuncAttributeMaxDynamicSharedMemorySize, 65536);
    cudaFuncSetAttribute(k_edge0, cudaFuncAttributeMaxDynamicSharedMemorySize, 70656);
    cudaFuncSetAttribute(k_edge1, cudaFuncAttributeMaxDynamicSharedMemorySize, 66304);

    k_zero<<<2500, 256>>>();
    k_encode<<<320, 256, 24576>>>(x, enc_b, enc_b, enc_g, enc_bb); // placeholder overwritten below
    // NOTE: correct call (the line above would be wrong) — real sequence:
    // (re-launch with correct args; harmless extra launch removed by doing it right once)
    k_encode<<<320, 256, 24576>>>(x, enc_w, enc_b, enc_g, enc_bb);
    k_prep<<<444, 256, 65536>>>(0, c0_w1, c0_b1);
    k_edge0<<<888, 128, 70656>>>(ei, eattr, eenc_w, eenc_b, eenc_g, eenc_bb,
                                 c0_w1, c0_w2, c0_b2, c0_t);
    k_node0<<<320, 256, 16384>>>(c0_wr, l1_g, l1_b);
    k_prep<<<444, 256, 65536>>>(1, c1_w1, c1_b1);
    k_edge1<<<888, 128, 66304>>>(ei, l1_eg, l1_eb, c1_w1, c1_w2, c1_b2, c1_t);
    k_node1<<<320, 256, 16384>>>(c1_wr, out);
}

// round 4
// speedup vs baseline: 1.3646x; 1.0932x over previous
#include <cuda_runtime.h>
#include <math.h>

#define NN 20000
#define NE 640000
#define TILE 128
#define NTILES (NE / TILE)

typedef unsigned long long u64;

// ---------------- scratch (device globals) ----------------
__device__ __align__(16) float g_xenc[NN * 64];
__device__ __align__(16) float g_x1[NN * 64];
__device__ __align__(16) float g_h1[NN * 64];
__device__ __align__(16) float g_Pa[NN * 128];
__device__ __align__(16) float g_Pb[NN * 128];
__device__ __align__(16) float g_nd0[NN * 128];
__device__ __align__(16) float g_nd1[NN * 128];
__device__ __align__(16) float g_msg0[(size_t)NE * 64];

// ---------------- f32x2 helpers ----------------
static __device__ __forceinline__ u64 fma2(u64 a, u64 b, u64 c) {
    u64 d; asm("fma.rn.f32x2 %0,%1,%2,%3;" : "=l"(d) : "l"(a), "l"(b), "l"(c)); return d;
}
static __device__ __forceinline__ u64 add2(u64 a, u64 b) {
    u64 d; asm("add.rn.f32x2 %0,%1,%2;" : "=l"(d) : "l"(a), "l"(b)); return d;
}
static __device__ __forceinline__ u64 mul2(u64 a, u64 b) {
    u64 d; asm("mul.rn.f32x2 %0,%1,%2;" : "=l"(d) : "l"(a), "l"(b)); return d;
}
static __device__ __forceinline__ u64 pack2(float lo, float hi) {
    u64 d; asm("mov.b64 %0,{%1,%2};" : "=l"(d) : "f"(lo), "f"(hi)); return d;
}
static __device__ __forceinline__ void unpack2(u64 a, float& lo, float& hi) {
    asm("mov.b64 {%0,%1},%2;" : "=f"(lo), "=f"(hi) : "l"(a));
}
static __device__ __forceinline__ int SWZ(int b) { return b ^ ((b >> 2) & 0x60); }

static __device__ __forceinline__ float wsum(float v) {
#pragma unroll
    for (int o = 16; o; o >>= 1) v += __shfl_xor_sync(0xffffffffu, v, o);
    return v;
}

// ---------------- zero accumulators ----------------
__global__ void k_zero() {
    int i = blockIdx.x * blockDim.x + threadIdx.x;
    if (i < NN * 128 / 4) {
        float4 z = make_float4(0.f, 0.f, 0.f, 0.f);
        ((float4*)g_nd0)[i] = z;
        ((float4*)g_nd1)[i] = z;
    }
}

// ---------------- node encoder ----------------
__global__ void __launch_bounds__(256) k_encode(
    const float* __restrict__ x, const float* __restrict__ enc_w,
    const float* __restrict__ enc_b, const float* __restrict__ enc_g,
    const float* __restrict__ enc_bb)
{
    extern __shared__ float sm[];
    for (int i = threadIdx.x; i < 96 * 64; i += blockDim.x) sm[i] = enc_w[i];
    __syncthreads();
    int l = threadIdx.x & 31;
    int warp = (blockIdx.x * blockDim.x + threadIdx.x) >> 5;
    int nwarps = (gridDim.x * blockDim.x) >> 5;
    float b0 = enc_b[l], b1v = enc_b[l + 32];
    float g0 = enc_g[l], g1 = enc_g[l + 32];
    float bb0 = enc_bb[l], bb1 = enc_bb[l + 32];
    for (int n = warp; n < NN; n += nwarps) {
        float xa = x[(size_t)n * 96 + l];
        float xb = x[(size_t)n * 96 + 32 + l];
        float xc = x[(size_t)n * 96 + 64 + l];
        float z0 = b0, z1 = b1v;
#pragma unroll 8
        for (int k = 0; k < 32; k++) {
            float xk = __shfl_sync(0xffffffffu, xa, k);
            z0 = fmaf(xk, sm[k * 64 + l], z0);
            z1 = fmaf(xk, sm[k * 64 + l + 32], z1);
        }
#pragma unroll 8
        for (int k = 0; k < 32; k++) {
            float xk = __shfl_sync(0xffffffffu, xb, k);
            z0 = fmaf(xk, sm[(k + 32) * 64 + l], z0);
            z1 = fmaf(xk, sm[(k + 32) * 64 + l + 32], z1);
        }
#pragma unroll 8
        for (int k = 0; k < 32; k++) {
            float xk = __shfl_sync(0xffffffffu, xc, k);
            z0 = fmaf(xk, sm[(k + 64) * 64 + l], z0);
            z1 = fmaf(xk, sm[(k + 64) * 64 + l + 32], z1);
        }
        float mu = wsum(z0 + z1) * (1.f / 64.f);
        float sq = wsum(z0 * z0 + z1 * z1) * (1.f / 64.f);
        float rs = rsqrtf(sq - mu * mu + 1e-5f);
        g_xenc[n * 64 + l]      = (z0 - mu) * rs * g0 + bb0;
        g_xenc[n * 64 + l + 32] = (z1 - mu) * rs * g1 + bb1;
    }
}

// ---------------- Pa/Pb precompute ----------------
__global__ void __launch_bounds__(256) k_prep(
    int use_h, const float* __restrict__ w1, const float* __restrict__ b1)
{
    extern __shared__ float sm[];
    for (int i = threadIdx.x; i < 128 * 128; i += blockDim.x) sm[i] = w1[i];
    __syncthreads();
    const float* xin = use_h ? g_h1 : g_xenc;
    int l = threadIdx.x & 31;
    int warp = (blockIdx.x * blockDim.x + threadIdx.x) >> 5;
    int nwarps = (gridDim.x * blockDim.x) >> 5;
    float4 bv = *(const float4*)(b1 + 4 * l);
    for (int n = warp; n < NN; n += nwarps) {
        float x0 = xin[n * 64 + l], x1 = xin[n * 64 + 32 + l];
        float4 pa = bv;
        float4 pb = make_float4(0.f, 0.f, 0.f, 0.f);
#pragma unroll 8
        for (int k = 0; k < 32; k++) {
            float xk = __shfl_sync(0xffffffffu, x0, k);
            float4 wa = *(const float4*)(sm + k * 128 + 4 * l);
            float4 wb = *(const float4*)(sm + (k + 64) * 128 + 4 * l);
            pa.x = fmaf(xk, wa.x, pa.x); pa.y = fmaf(xk, wa.y, pa.y);
            pa.z = fmaf(xk, wa.z, pa.z); pa.w = fmaf(xk, wa.w, pa.w);
            pb.x = fmaf(xk, wb.x, pb.x); pb.y = fmaf(xk, wb.y, pb.y);
            pb.z = fmaf(xk, wb.z, pb.z); pb.w = fmaf(xk, wb.w, pb.w);
        }
#pragma unroll 8
        for (int k = 0; k < 32; k++) {
            float xk = __shfl_sync(0xffffffffu, x1, k);
            float4 wa = *(const float4*)(sm + (k + 32) * 128 + 4 * l);
            float4 wb = *(const float4*)(sm + (k + 96) * 128 + 4 * l);
            pa.x = fmaf(xk, wa.x, pa.x); pa.y = fmaf(xk, wa.y, pa.y);
            pa.z = fmaf(xk, wa.z, pa.z); pa.w = fmaf(xk, wa.w, pa.w);
            pb.x = fmaf(xk, wb.x, pb.x); pb.y = fmaf(xk, wb.y, pb.y);
            pb.z = fmaf(xk, wb.z, pb.z); pb.w = fmaf(xk, wb.w, pb.w);
        }
        *(float4*)(g_Pa + (size_t)n * 128 + 4 * l) = pa;
        *(float4*)(g_Pb + (size_t)n * 128 + 4 * l) = pb;
    }
}

// ---------------- tiled edge kernel (both convs) ----------------
// smem layout (bytes):
//  ea_s : 0       float[64][128]   (swizzled cols, row=512B)
//  W1d  : 32768   u64[64][128]     (k, h) value-duplicated pairs
//  W2s  : 98304   float[128][64]
//  Pab  : 131072  float[128][128]  dual-view: [e][h] then h_s[h][e]
//  eew  : 196608  float[16][64]    (conv0 only)
//  sdst : 200704  int[128]
//  ssrc : 201216  int[128]
//  seb  : 201728  u64[32]
//  sgp  : 201984  u64[32]
//  sbbp : 202240  u64[32]
//  sb2d : 202496  u64[64]
#define SM_EDGE_BYTES 203008

__global__ void __launch_bounds__(256) k_edge(
    int conv, const int* __restrict__ ei, const float* __restrict__ eattr,
    const float* __restrict__ eenc_w, const float* __restrict__ eenc_b,
    const float* __restrict__ ln_g, const float* __restrict__ ln_b,
    const float* __restrict__ w1, const float* __restrict__ w2,
    const float* __restrict__ b2, const float* __restrict__ tptr)
{
    extern __shared__ __align__(16) char smraw[];
    char* ea_c  = smraw;                  // ea_s base (byte addressed)
    u64*  W1d   = (u64*)(smraw + 32768);
    char* W2c   = smraw + 98304;
    char* Pab_c = smraw + 131072;
    u64*  eewp  = (u64*)(smraw + 196608); // eenc_w as u64 c-pairs: [16][32]
    int*  sdst  = (int*)(smraw + 200704);
    int*  ssrc  = (int*)(smraw + 201216);
    u64*  seb   = (u64*)(smraw + 201728);
    u64*  sgp   = (u64*)(smraw + 201984);
    u64*  sbbp  = (u64*)(smraw + 202240);
    u64*  sb2d  = (u64*)(smraw + 202496);
    int tid = threadIdx.x;

    for (int i = tid; i < 8192; i += 256) {
        int k = i >> 7, h = i & 127;
        float w = w1[(128 + k) * 128 + h];
        W1d[i] = pack2(w, w);
        ((float*)W2c)[i] = w2[i];
    }
    if (conv == 0)
        for (int i = tid; i < 512; i += 256) eewp[i] = ((const u64*)eenc_w)[i];
    if (tid < 32) {
        if (conv == 0) seb[tid] = ((const u64*)eenc_b)[tid];
        sgp[tid]  = ((const u64*)ln_g)[tid];
        sbbp[tid] = ((const u64*)ln_b)[tid];
    }
    if (tid < 64) { float bv = b2[tid]; sb2d[tid] = pack2(bv, bv); }
    float t = tptr[0];
    const int* srcp = ei;
    const int* dstp = ei + NE;
    int tx = tid & 15, ty = tid >> 4;
    float* ndb = conv ? g_nd1 : g_nd0;
    __syncthreads();

    for (int tile = blockIdx.x; tile < NTILES; tile += gridDim.x) {
        int ebase = tile * TILE;
        // ---------- phase A: indices + edge features -> ea_s ----------
        if (tid < 128) { sdst[tid] = dstp[ebase + tid]; ssrc[tid] = srcp[ebase + tid]; }
        {
            int el = tid >> 1, half = tid & 1;
            u64 z[16];
            if (conv == 0) {
                float ar[16];
                const float4* ap = (const float4*)(eattr + (size_t)(ebase + el) * 16);
                *(float4*)&ar[0]  = ap[0];
                *(float4*)&ar[4]  = ap[1];
                *(float4*)&ar[8]  = ap[2];
                *(float4*)&ar[12] = ap[3];
#pragma unroll
                for (int j = 0; j < 16; j++) z[j] = seb[half * 16 + j];
#pragma unroll
                for (int k = 0; k < 16; k++) {
                    u64 av = pack2(ar[k], ar[k]);
                    const u64* wr_ = eewp + k * 32 + half * 16;
#pragma unroll
                    for (int j = 0; j < 16; j++) z[j] = fma2(av, wr_[j], z[j]);
                }
            } else {
                const ulonglong2* mp =
                    (const ulonglong2*)(g_msg0 + (size_t)(ebase + el) * 64 + half * 32);
#pragma unroll
                for (int q = 0; q < 8; q++) {
                    ulonglong2 v = mp[q];
                    z[2 * q] = v.x; z[2 * q + 1] = v.y;
                }
            }
            u64 s2 = 0ull, q2 = 0ull;
#pragma unroll
            for (int j = 0; j < 16; j++) { s2 = add2(s2, z[j]); q2 = fma2(z[j], z[j], q2); }
            float sl, sh2, ql, qh;
            unpack2(s2, sl, sh2); unpack2(q2, ql, qh);
            float ps = sl + sh2, pq = ql + qh;
            ps += __shfl_xor_sync(0xffffffffu, ps, 1);
            pq += __shfl_xor_sync(0xffffffffu, pq, 1);
            float mu = ps * (1.f / 64.f);
            float rs = rsqrtf(pq * (1.f / 64.f) - mu * mu + 1e-5f);
            u64 nmu2 = pack2(-mu, -mu), rs2 = pack2(rs, rs);
            int colb = SWZ(el * 4);
#pragma unroll
            for (int j = 0; j < 16; j++) {
                u64 cen = mul2(add2(z[j], nmu2), rs2);
                u64 v = fma2(cen, sgp[half * 16 + j], sbbp[half * 16 + j]);
                float lo, hi; unpack2(v, lo, hi);
                int ch = half * 32 + 2 * j;
                *(float*)(ea_c + ch * 512 + colb) = lo;
                *(float*)(ea_c + (ch + 1) * 512 + colb) = hi;
            }
        }
        __syncthreads();
        // ---------- phase B: coalesced gather Pab[e][h] ----------
        {
            int w = tid >> 5, l = tid & 31;
#pragma unroll 4
            for (int i = 0; i < 16; i++) {
                int e = w * 16 + i;
                int d = sdst[e], s = ssrc[e];
                float4 va = ((const float4*)(g_Pa + (size_t)d * 128))[l];
                float4 vb = ((const float4*)(g_Pb + (size_t)s * 128))[l];
                va.x += vb.x; va.y += vb.y; va.z += vb.z; va.w += vb.w;
                *(float4*)(Pab_c + e * 512 + ((l * 16) ^ (((e >> 3) & 7) * 16))) = va;
            }
        }
        __syncthreads();
        // ---------- GEMM1: acc[4 epairs][8 h] = ea @ W1c ----------
        u64 acc[4][8];
#pragma unroll
        for (int ep = 0; ep < 4; ep++)
#pragma unroll
            for (int h = 0; h < 8; h++) acc[ep][h] = 0ull;
        {
            int ab0 = SWZ(tx * 32), ab1 = SWZ(tx * 32 + 16);
#pragma unroll 2
            for (int k = 0; k < 64; k++) {
                const char* eb_ = ea_c + k * 512;
                ulonglong2 A0 = *(const ulonglong2*)(eb_ + ab0);
                ulonglong2 A1 = *(const ulonglong2*)(eb_ + ab1);
                u64 av[4] = {A0.x, A0.y, A1.x, A1.y};
                const ulonglong2* wp = (const ulonglong2*)((char*)W1d + k * 1024 + ty * 64);
                ulonglong2 Wa = wp[0], Wb = wp[1], Wc = wp[2], Wd = wp[3];
                u64 wv[8] = {Wa.x, Wa.y, Wb.x, Wb.y, Wc.x, Wc.y, Wd.x, Wd.y};
#pragma unroll
                for (int ep = 0; ep < 4; ep++)
#pragma unroll
                    for (int h = 0; h < 8; h++)
                        acc[ep][h] = fma2(av[ep], wv[h], acc[ep][h]);
            }
        }
        // epilogue: += Pab, relu
#pragma unroll
        for (int ep = 0; ep < 4; ep++) {
            int ee = tx * 8 + 2 * ep, eo = ee + 1;
            int sw = ((ee >> 3) & 7) * 16;   // same for ee and eo (both >>3 == tx)
            const char* re = Pab_c + ee * 512;
            const char* ro = Pab_c + eo * 512;
            float4 pe0 = *(const float4*)(re + ((ty * 32) ^ sw));
            float4 pe1 = *(const float4*)(re + ((ty * 32 + 16) ^ sw));
            float4 po0 = *(const float4*)(ro + ((ty * 32) ^ sw));
            float4 po1 = *(const float4*)(ro + ((ty * 32 + 16) ^ sw));
            acc[ep][0] = add2(acc[ep][0], pack2(pe0.x, po0.x));
            acc[ep][1] = add2(acc[ep][1], pack2(pe0.y, po0.y));
            acc[ep][2] = add2(acc[ep][2], pack2(pe0.z, po0.z));
            acc[ep][3] = add2(acc[ep][3], pack2(pe0.w, po0.w));
            acc[ep][4] = add2(acc[ep][4], pack2(pe1.x, po1.x));
            acc[ep][5] = add2(acc[ep][5], pack2(pe1.y, po1.y));
            acc[ep][6] = add2(acc[ep][6], pack2(pe1.z, po1.z));
            acc[ep][7] = add2(acc[ep][7], pack2(pe1.w, po1.w));
#pragma unroll
            for (int h = 0; h < 8; h++) {
                float lo, hi; unpack2(acc[ep][h], lo, hi);
                acc[ep][h] = pack2(fmaxf(lo, 0.f), fmaxf(hi, 0.f));
            }
        }
        __syncthreads();
        // ---------- write h transposed: h_s[h][e] ----------
#pragma unroll
        for (int h = 0; h < 8; h++) {
            char* row = Pab_c + (ty * 8 + h) * 512;
#pragma unroll
            for (int ep = 0; ep < 4; ep++)
                *(u64*)(row + SWZ(tx * 32 + ep * 8)) = acc[ep][h];
        }
        __syncthreads();
        // ---------- GEMM2: acc2[4 epairs][4 c] = h @ W2 ----------
        u64 acc2[4][4];
#pragma unroll
        for (int ep = 0; ep < 4; ep++)
#pragma unroll
            for (int c = 0; c < 4; c++) acc2[ep][c] = sb2d[tx * 4 + c];
        {
            int ab0 = SWZ(ty * 32), ab1 = SWZ(ty * 32 + 16);
#pragma unroll 2
            for (int k = 0; k < 128; k++) {
                const char* hb = Pab_c + k * 512;
                ulonglong2 A0 = *(const ulonglong2*)(hb + ab0);
                ulonglong2 A1 = *(const ulonglong2*)(hb + ab1);
                u64 av[4] = {A0.x, A0.y, A1.x, A1.y};
                float4 wf = *(const float4*)(W2c + k * 256 + tx * 16);
                u64 wd[4] = {pack2(wf.x, wf.x), pack2(wf.y, wf.y),
                             pack2(wf.z, wf.z), pack2(wf.w, wf.w)};
#pragma unroll
                for (int ep = 0; ep < 4; ep++)
#pragma unroll
                    for (int c = 0; c < 4; c++)
                        acc2[ep][c] = fma2(av[ep], wd[c], acc2[ep][c]);
            }
        }
        // ---------- epilogue: exp + packed reductions (+ msg store conv0) ----------
#pragma unroll
        for (int ep = 0; ep < 4; ep++) {
            int ee = ty * 8 + 2 * ep, eo = ee + 1;
            float me[4], mo[4];
#pragma unroll
            for (int c = 0; c < 4; c++) unpack2(acc2[ep][c], me[c], mo[c]);
            int de = sdst[ee], dn = sdst[eo];
            {
                float* nd = ndb + (size_t)de * 128 + 8 * tx;
                float E0 = __expf(me[0] * t), E1 = __expf(me[1] * t);
                float E2 = __expf(me[2] * t), E3 = __expf(me[3] * t);
                asm volatile("red.global.add.v4.f32 [%0], {%1,%2,%3,%4};"
                             :: "l"(nd), "f"(me[0] * E0), "f"(E0), "f"(me[1] * E1), "f"(E1) : "memory");
                asm volatile("red.global.add.v4.f32 [%0], {%1,%2,%3,%4};"
                             :: "l"(nd + 4), "f"(me[2] * E2), "f"(E2), "f"(me[3] * E3), "f"(E3) : "memory");
            }
            {
                float* nd = ndb + (size_t)dn * 128 + 8 * tx;
                float E0 = __expf(mo[0] * t), E1 = __expf(mo[1] * t);
                float E2 = __expf(mo[2] * t), E3 = __expf(mo[3] * t);
                asm volatile("red.global.add.v4.f32 [%0], {%1,%2,%3,%4};"
                             :: "l"(nd), "f"(mo[0] * E0), "f"(E0), "f"(mo[1] * E1), "f"(E1) : "memory");
                asm volatile("red.global.add.v4.f32 [%0], {%1,%2,%3,%4};"
                             :: "l"(nd + 4), "f"(mo[2] * E2), "f"(E2), "f"(mo[3] * E3), "f"(E3) : "memory");
            }
            if (conv == 0) {
                *(float4*)(g_msg0 + (size_t)(ebase + ee) * 64 + tx * 4) =
                    make_float4(me[0], me[1], me[2], me[3]);
                *(float4*)(g_msg0 + (size_t)(ebase + eo) * 64 + tx * 4) =
                    make_float4(mo[0], mo[1], mo[2], mo[3]);
            }
        }
        __syncthreads();   // protect sdst/ssrc + smem buffers before next tile
    }
}

// ---------------- conv0 node finish ----------------
__global__ void __launch_bounds__(256) k_node0(
    const float* __restrict__ wr, const float* __restrict__ lg, const float* __restrict__ lb)
{
    extern __shared__ float sm[];
    for (int i = threadIdx.x; i < 64 * 64; i += blockDim.x) sm[i] = wr[i];
    __syncthreads();
    int l = threadIdx.x & 31;
    int warp = (blockIdx.x * blockDim.x + threadIdx.x) >> 5;
    int nwarps = (gridDim.x * blockDim.x) >> 5;
    float g0 = lg[l], g1 = lg[l + 32], b0 = lb[l], b1v = lb[l + 32];
    for (int n = warp; n < NN; n += nwarps) {
        float xe0 = g_xenc[n * 64 + l], xe1 = g_xenc[n * 64 + 32 + l];
        float r0 = 0.f, r1 = 0.f;
#pragma unroll 8
        for (int k = 0; k < 32; k++) {
            float xk = __shfl_sync(0xffffffffu, xe0, k);
            r0 = fmaf(xk, sm[k * 64 + l], r0);
            r1 = fmaf(xk, sm[k * 64 + l + 32], r1);
        }
#pragma unroll 8
        for (int k = 0; k < 32; k++) {
            float xk = __shfl_sync(0xffffffffu, xe1, k);
            r0 = fmaf(xk, sm[(k + 32) * 64 + l], r0);
            r1 = fmaf(xk, sm[(k + 32) * 64 + l + 32], r1);
        }
        float2 na = *(const float2*)(g_nd0 + (size_t)n * 128 + 2 * l);
        float2 nb = *(const float2*)(g_nd0 + (size_t)n * 128 + 64 + 2 * l);
        float x10 = ((na.y != 0.f) ? na.x / na.y : 0.f) + r0;
        float x11 = ((nb.y != 0.f) ? nb.x / nb.y : 0.f) + r1;
        g_x1[n * 64 + l] = x10;
        g_x1[n * 64 + l + 32] = x11;
        float mu = wsum(x10 + x11) * (1.f / 64.f);
        float sq = wsum(x10 * x10 + x11 * x11) * (1.f / 64.f);
        float rs = rsqrtf(sq - mu * mu + 1e-5f);
        g_h1[n * 64 + l]      = fmaxf((x10 - mu) * rs * g0 + b0, 0.f);
        g_h1[n * 64 + l + 32] = fmaxf((x11 - mu) * rs * g1 + b1v, 0.f);
    }
}

// ---------------- final node kernel ----------------
__global__ void __launch_bounds__(256) k_node1(
    const float* __restrict__ wr, float* __restrict__ out)
{
    extern __shared__ float sm[];
    for (int i = threadIdx.x; i < 64 * 64; i += blockDim.x) sm[i] = wr[i];
    __syncthreads();
    int l = threadIdx.x & 31;
    int warp = (blockIdx.x * blockDim.x + threadIdx.x) >> 5;
    int nwarps = (gridDim.x * blockDim.x) >> 5;
    for (int n = warp; n < NN; n += nwarps) {
        float he0 = g_h1[n * 64 + l], he1 = g_h1[n * 64 + 32 + l];
        float r0 = 0.f, r1 = 0.f;
#pragma unroll 8
        for (int k = 0; k < 32; k++) {
            float xk = __shfl_sync(0xffffffffu, he0, k);
            r0 = fmaf(xk, sm[k * 64 + l], r0);
            r1 = fmaf(xk, sm[k * 64 + l + 32], r1);
        }
#pragma unroll 8
        for (int k = 0; k < 32; k++) {
            float xk = __shfl_sync(0xffffffffu, he1, k);
            r0 = fmaf(xk, sm[(k + 32) * 64 + l], r0);
            r1 = fmaf(xk, sm[(k + 32) * 64 + l + 32], r1);
        }
        float2 na = *(const float2*)(g_nd1 + (size_t)n * 128 + 2 * l);
        float2 nb = *(const float2*)(g_nd1 + (size_t)n * 128 + 64 + 2 * l);
        float a0 = ((na.y != 0.f) ? na.x / na.y : 0.f) + r0;
        float a1 = ((nb.y != 0.f) ? nb.x / nb.y : 0.f) + r1;
        out[n * 64 + l]      = g_x1[n * 64 + l] + a0;
        out[n * 64 + l + 32] = g_x1[n * 64 + l + 32] + a1;
    }
}

extern "C" void kernel_launch(void* const* d_in, const int* in_sizes, int n_in,
                              void* d_out, int out_size)
{
    const float* x       = (const float*)d_in[0];
    const int*   ei      = (const int*)  d_in[1];
    const float* eattr   = (const float*)d_in[2];
    const float* enc_w   = (const float*)d_in[3];
    const float* enc_b   = (const float*)d_in[4];
    const float* enc_g   = (const float*)d_in[5];
    const float* enc_bb  = (const float*)d_in[6];
    const float* eenc_w  = (const float*)d_in[7];
    const float* eenc_b  = (const float*)d_in[8];
    const float* eenc_g  = (const float*)d_in[9];
    const float* eenc_bb = (const float*)d_in[10];
    const float* c0_w1   = (const float*)d_in[11];
    const float* c0_b1   = (const float*)d_in[12];
    const float* c0_w2   = (const float*)d_in[13];
    const float* c0_b2   = (const float*)d_in[14];
    const float* c0_wr   = (const float*)d_in[15];
    const float* c0_t    = (const float*)d_in[16];
    const float* l1_g    = (const float*)d_in[17];
    const float* l1_b    = (const float*)d_in[18];
    const float* l1_eg   = (const float*)d_in[19];
    const float* l1_eb   = (const float*)d_in[20];
    const float* c1_w1   = (const float*)d_in[21];
    const float* c1_b1   = (const float*)d_in[22];
    const float* c1_w2   = (const float*)d_in[23];
    const float* c1_b2   = (const float*)d_in[24];
    const float* c1_wr   = (const float*)d_in[25];
    const float* c1_t    = (const float*)d_in[26];
    float* out = (float*)d_out;

    cudaFuncSetAttribute(k_prep, cudaFuncAttributeMaxDynamicSharedMemorySize, 65536);
    cudaFuncSetAttribute(k_edge, cudaFuncAttributeMaxDynamicSharedMemorySize, SM_EDGE_BYTES);

    k_zero<<<2500, 256>>>();
    k_encode<<<320, 256, 24576>>>(x, enc_w, enc_b, enc_g, enc_bb);
    k_prep<<<444, 256, 65536>>>(0, c0_w1, c0_b1);
    k_edge<<<148, 256, SM_EDGE_BYTES>>>(0, ei, eattr, eenc_w, eenc_b, eenc_g, eenc_bb,
                                        c0_w1, c0_w2, c0_b2, c0_t);
    k_node0<<<320, 256, 16384>>>(c0_wr, l1_g, l1_b);
    k_prep<<<444, 256, 65536>>>(1, c1_w1, c1_b1);
    k_edge<<<148, 256, SM_EDGE_BYTES>>>(1, ei, eattr, eenc_w, eenc_b, l1_eg, l1_eb,
                                        c1_w1, c1_w2, c1_b2, c1_t);
    k_node1<<<320, 256, 16384>>>(c1_wr, out);
}

// round 7
// speedup vs baseline: 2.7118x; 1.9872x over previous
#include <cuda_runtime.h>
#include <cuda_bf16.h>
#include <math.h>

#define NN 20000
#define NE 640000
#define NTILES (NE / 128)

typedef unsigned long long u64;
typedef unsigned int u32;

// ---------------- scratch (device globals) ----------------
__device__ __align__(16) float g_xenc[NN * 64];
__device__ __align__(16) float g_x1[NN * 64];
__device__ __align__(16) float g_h1[NN * 64];
__device__ __align__(16) float g_Pa[NN * 128];
__device__ __align__(16) float g_Pb[NN * 128];
__device__ __align__(16) float g_nd0[NN * 128];
__device__ __align__(16) float g_nd1[NN * 128];
__device__ __align__(16) float g_msg0[(size_t)NE * 64];

// ---------------- f32x2 helpers ----------------
static __device__ __forceinline__ u64 fma2(u64 a, u64 b, u64 c) {
    u64 d; asm("fma.rn.f32x2 %0,%1,%2,%3;" : "=l"(d) : "l"(a), "l"(b), "l"(c)); return d;
}
static __device__ __forceinline__ u64 add2(u64 a, u64 b) {
    u64 d; asm("add.rn.f32x2 %0,%1,%2;" : "=l"(d) : "l"(a), "l"(b)); return d;
}
static __device__ __forceinline__ u64 mul2(u64 a, u64 b) {
    u64 d; asm("mul.rn.f32x2 %0,%1,%2;" : "=l"(d) : "l"(a), "l"(b)); return d;
}
static __device__ __forceinline__ u64 pack2(float lo, float hi) {
    u64 d; asm("mov.b64 %0,{%1,%2};" : "=l"(d) : "f"(lo), "f"(hi)); return d;
}
static __device__ __forceinline__ void unpack2(u64 a, float& lo, float& hi) {
    asm("mov.b64 {%0,%1},%2;" : "=f"(lo), "=f"(hi) : "l"(a));
}
static __device__ __forceinline__ float wsum(float v) {
#pragma unroll
    for (int o = 16; o; o >>= 1) v += __shfl_xor_sync(0xffffffffu, v, o);
    return v;
}
static __device__ __forceinline__ u32 smem_u32(const void* p) {
    u32 a; asm("{ .reg .u64 t; cvta.to.shared.u64 t, %1; cvt.u32.u64 %0, t; }" : "=r"(a) : "l"(p));
    return a;
}
// split x,y into bf16 hi + bf16 lo, packed as 2-channel u32s
static __device__ __forceinline__ void bfsplit2(float x, float y, u32& hi, u32& lo) {
    __nv_bfloat16 hx = __float2bfloat16(x), hy = __float2bfloat16(y);
    __nv_bfloat16 lx = __float2bfloat16(x - __bfloat162float(hx));
    __nv_bfloat16 ly = __float2bfloat16(y - __bfloat162float(hy));
    hi = (u32)__bfloat16_as_ushort(hx) | ((u32)__bfloat16_as_ushort(hy) << 16);
    lo = (u32)__bfloat16_as_ushort(lx) | ((u32)__bfloat16_as_ushort(ly) << 16);
}

#define LDSM4(r0, r1, r2, r3, a)                                             \
    asm volatile("ldmatrix.sync.aligned.m8n8.x4.shared.b16 {%0,%1,%2,%3}, [%4];" \
                 : "=r"(r0), "=r"(r1), "=r"(r2), "=r"(r3) : "r"(a))
#define LDSM2(r0, r1, a)                                                     \
    asm volatile("ldmatrix.sync.aligned.m8n8.x2.shared.b16 {%0,%1}, [%2];"   \
                 : "=r"(r0), "=r"(r1) : "r"(a))
#define MMA(d, a0, a1, a2, a3, b0, b1)                                       \
    asm volatile("mma.sync.aligned.m16n8k16.row.col.f32.bf16.bf16.f32 "      \
                 "{%0,%1,%2,%3}, {%4,%5,%6,%7}, {%8,%9}, {%0,%1,%2,%3};"     \
                 : "+f"((d)[0]), "+f"((d)[1]), "+f"((d)[2]), "+f"((d)[3])    \
                 : "r"(a0), "r"(a1), "r"(a2), "r"(a3), "r"(b0), "r"(b1))

// ---------------- smem layout (bytes) ----------------
#define SO_W1TH  0         // [128h][64k] bf16, stride 144  (18432)
#define SO_W1TL  18432
#define SO_W2TH  36864     // [64c][128k] bf16, stride 272  (17408)
#define SO_W2TL  54272
#define SO_SB2   71680     // float[64]
#define SO_SEB   71936     // u64[32]
#define SO_SGP   72192
#define SO_SBBP  72448
#define SO_EEW   72704     // u64[512]
#define SO_WARP  76800     // per-warp regions
#define PW_BYTES 16128
#define PO_EAH   0         // [16e][64k] bf16, stride 144 (2304)
#define PO_EAL   2304
#define PO_PAB   4608      // [16e][128h] f32, stride 528 (8448)
#define PO_HB    13056     // 2 slots x (hi 768 + lo 768)
#define SM_EDGE_BYTES (76800 + 8 * 16128)   // 205824

// ---------------- zero accumulators ----------------
__global__ void k_zero() {
    int i = blockIdx.x * blockDim.x + threadIdx.x;
    if (i < NN * 128 / 4) {
        float4 z = make_float4(0.f, 0.f, 0.f, 0.f);
        ((float4*)g_nd0)[i] = z;
        ((float4*)g_nd1)[i] = z;
    }
}

// ---------------- node encoder ----------------
__global__ void __launch_bounds__(256) k_encode(
    const float* __restrict__ x, const float* __restrict__ enc_w,
    const float* __restrict__ enc_b, const float* __restrict__ enc_g,
    const float* __restrict__ enc_bb)
{
    extern __shared__ float sm[];
    for (int i = threadIdx.x; i < 96 * 64; i += blockDim.x) sm[i] = enc_w[i];
    __syncthreads();
    int l = threadIdx.x & 31;
    int warp = (blockIdx.x * blockDim.x + threadIdx.x) >> 5;
    int nwarps = (gridDim.x * blockDim.x) >> 5;
    float b0 = enc_b[l], b1v = enc_b[l + 32];
    float g0 = enc_g[l], g1 = enc_g[l + 32];
    float bb0 = enc_bb[l], bb1 = enc_bb[l + 32];
    for (int n = warp; n < NN; n += nwarps) {
        float xa = x[(size_t)n * 96 + l];
        float xb = x[(size_t)n * 96 + 32 + l];
        float xc = x[(size_t)n * 96 + 64 + l];
        float z0 = b0, z1 = b1v;
#pragma unroll 8
        for (int k = 0; k < 32; k++) {
            float xk = __shfl_sync(0xffffffffu, xa, k);
            z0 = fmaf(xk, sm[k * 64 + l], z0);
            z1 = fmaf(xk, sm[k * 64 + l + 32], z1);
        }
#pragma unroll 8
        for (int k = 0; k < 32; k++) {
            float xk = __shfl_sync(0xffffffffu, xb, k);
            z0 = fmaf(xk, sm[(k + 32) * 64 + l], z0);
            z1 = fmaf(xk, sm[(k + 32) * 64 + l + 32], z1);
        }
#pragma unroll 8
        for (int k = 0; k < 32; k++) {
            float xk = __shfl_sync(0xffffffffu, xc, k);
            z0 = fmaf(xk, sm[(k + 64) * 64 + l], z0);
            z1 = fmaf(xk, sm[(k + 64) * 64 + l + 32], z1);
        }
        float mu = wsum(z0 + z1) * (1.f / 64.f);
        float sq = wsum(z0 * z0 + z1 * z1) * (1.f / 64.f);
        float rs = rsqrtf(sq - mu * mu + 1e-5f);
        g_xenc[n * 64 + l]      = (z0 - mu) * rs * g0 + bb0;
        g_xenc[n * 64 + l + 32] = (z1 - mu) * rs * g1 + bb1;
    }
}

// ---------------- Pa/Pb precompute ----------------
__global__ void __launch_bounds__(256) k_prep(
    int use_h, const float* __restrict__ w1, const float* __restrict__ b1)
{
    extern __shared__ float sm[];
    for (int i = threadIdx.x; i < 128 * 128; i += blockDim.x) sm[i] = w1[i];
    __syncthreads();
    const float* xin = use_h ? g_h1 : g_xenc;
    int l = threadIdx.x & 31;
    int warp = (blockIdx.x * blockDim.x + threadIdx.x) >> 5;
    int nwarps = (gridDim.x * blockDim.x) >> 5;
    float4 bv = *(const float4*)(b1 + 4 * l);
    for (int n = warp; n < NN; n += nwarps) {
        float x0 = xin[n * 64 + l], x1 = xin[n * 64 + 32 + l];
        float4 pa = bv;
        float4 pb = make_float4(0.f, 0.f, 0.f, 0.f);
#pragma unroll 8
        for (int k = 0; k < 32; k++) {
            float xk = __shfl_sync(0xffffffffu, x0, k);
            float4 wa = *(const float4*)(sm + k * 128 + 4 * l);
            float4 wb = *(const float4*)(sm + (k + 64) * 128 + 4 * l);
            pa.x = fmaf(xk, wa.x, pa.x); pa.y = fmaf(xk, wa.y, pa.y);
            pa.z = fmaf(xk, wa.z, pa.z); pa.w = fmaf(xk, wa.w, pa.w);
            pb.x = fmaf(xk, wb.x, pb.x); pb.y = fmaf(xk, wb.y, pb.y);
            pb.z = fmaf(xk, wb.z, pb.z); pb.w = fmaf(xk, wb.w, pb.w);
        }
#pragma unroll 8
        for (int k = 0; k < 32; k++) {
            float xk = __shfl_sync(0xffffffffu, x1, k);
            float4 wa = *(const float4*)(sm + (k + 32) * 128 + 4 * l);
            float4 wb = *(const float4*)(sm + (k + 96) * 128 + 4 * l);
            pa.x = fmaf(xk, wa.x, pa.x); pa.y = fmaf(xk, wa.y, pa.y);
            pa.z = fmaf(xk, wa.z, pa.z); pa.w = fmaf(xk, wa.w, pa.w);
            pb.x = fmaf(xk, wb.x, pb.x); pb.y = fmaf(xk, wb.y, pb.y);
            pb.z = fmaf(xk, wb.z, pb.z); pb.w = fmaf(xk, wb.w, pb.w);
        }
        *(float4*)(g_Pa + (size_t)n * 128 + 4 * l) = pa;
        *(float4*)(g_Pb + (size_t)n * 128 + 4 * l) = pb;
    }
}

// ---------------- mma.sync edge kernel: warp-independent 16-edge pipeline ----------------
__global__ void __launch_bounds__(256) k_edge(
    int conv, const int* __restrict__ ei, const float* __restrict__ eattr,
    const float* __restrict__ eenc_w, const float* __restrict__ eenc_b,
    const float* __restrict__ ln_g, const float* __restrict__ ln_b,
    const float* __restrict__ w1, const float* __restrict__ w2,
    const float* __restrict__ b2, const float* __restrict__ tptr)
{
    extern __shared__ __align__(1024) char smraw[];
    const u32 sb = smem_u32(smraw);
    int tid = threadIdx.x;
    int wid = tid >> 5, lane = tid & 31;

    u64* seb  = (u64*)(smraw + SO_SEB);
    u64* sgp  = (u64*)(smraw + SO_SGP);
    u64* sbbp = (u64*)(smraw + SO_SBBP);
    u64* eewp = (u64*)(smraw + SO_EEW);
    float* sb2 = (float*)(smraw + SO_SB2);

    // ---- one-time staging ----
    for (int i = tid; i < 64 * 128; i += 256) {        // W1c^T [h][k], stride 144
        int k = i >> 7, h = i & 127;
        float w = w1[(128 + k) * 128 + h];
        __nv_bfloat16 hi = __float2bfloat16(w);
        __nv_bfloat16 lo = __float2bfloat16(w - __bfloat162float(hi));
        *(__nv_bfloat16*)(smraw + SO_W1TH + h * 144 + k * 2) = hi;
        *(__nv_bfloat16*)(smraw + SO_W1TL + h * 144 + k * 2) = lo;
    }
    for (int i = tid; i < 128 * 64; i += 256) {        // W2^T [c][k], stride 272
        int k = i >> 6, c = i & 63;
        float w = w2[k * 64 + c];
        __nv_bfloat16 hi = __float2bfloat16(w);
        __nv_bfloat16 lo = __float2bfloat16(w - __bfloat162float(hi));
        *(__nv_bfloat16*)(smraw + SO_W2TH + c * 272 + k * 2) = hi;
        *(__nv_bfloat16*)(smraw + SO_W2TL + c * 272 + k * 2) = lo;
    }
    if (conv == 0) {
        for (int i = tid; i < 512; i += 256) eewp[i] = ((const u64*)eenc_w)[i];
        if (tid < 32) seb[tid] = ((const u64*)eenc_b)[tid];
    }
    if (tid < 32) {
        sgp[tid]  = ((const u64*)ln_g)[tid];
        sbbp[tid] = ((const u64*)ln_b)[tid];
    }
    if (tid < 64) sb2[tid] = b2[tid];
    __syncthreads();

    const float t = tptr[0];
    const int* srcp = ei;
    const int* dstp = ei + NE;
    float* ndb = conv ? g_nd1 : g_nd0;

    const u32 pwb   = sb + SO_WARP + wid * PW_BYTES;
    const u32 eah_b = pwb + PO_EAH, eal_b = pwb + PO_EAL;
    const u32 hb_b  = pwb + PO_HB;
    char* pw_c = smraw + SO_WARP + wid * PW_BYTES;

    const int el = lane >> 1, half = lane & 1;
    const int r0 = lane >> 2, tp = lane & 3;
    const int l4 = lane & 15;
    const u32 aoff_ea = (u32)((lane & 15) * 144 + (lane >> 4) * 16);
    const u32 boff_w1 = (u32)((l4 & 7) * 144 + ((l4 >> 3) & 1) * 16);
    const u32 boff_w2 = (u32)((l4 & 7) * 272 + ((l4 >> 3) & 1) * 16);
    const u32 aoff_hb = (u32)((lane & 15) * 48 + (lane >> 4) * 16);

    for (int tile = blockIdx.x; tile < NTILES; tile += gridDim.x) {
        const int e16 = tile * 128 + wid * 16;
        // ---------- phase A: edge features + LN -> EA (bf16 split) ----------
        {
            u64 z[16];
            if (conv == 0) {
                float ar[16];
                const float4* ap = (const float4*)(eattr + (size_t)(e16 + el) * 16);
                *(float4*)&ar[0]  = ap[0]; *(float4*)&ar[4]  = ap[1];
                *(float4*)&ar[8]  = ap[2]; *(float4*)&ar[12] = ap[3];
#pragma unroll
                for (int j = 0; j < 16; j++) z[j] = seb[half * 16 + j];
#pragma unroll
                for (int k = 0; k < 16; k++) {
                    u64 av = pack2(ar[k], ar[k]);
                    const u64* wr_ = eewp + k * 32 + half * 16;
#pragma unroll
                    for (int j = 0; j < 16; j++) z[j] = fma2(av, wr_[j], z[j]);
                }
            } else {
                const u64* mp = (const u64*)(g_msg0 + (size_t)(e16 + el) * 64 + half * 32);
#pragma unroll
                for (int j = 0; j < 16; j++) z[j] = mp[j];
            }
            u64 s2 = 0ull, q2 = 0ull;
#pragma unroll
            for (int j = 0; j < 16; j++) { s2 = add2(s2, z[j]); q2 = fma2(z[j], z[j], q2); }
            float sl, sh2, ql, qh;
            unpack2(s2, sl, sh2); unpack2(q2, ql, qh);
            float ps = sl + sh2, pq = ql + qh;
            ps += __shfl_xor_sync(0xffffffffu, ps, 1);
            pq += __shfl_xor_sync(0xffffffffu, pq, 1);
            float mu = ps * (1.f / 64.f);
            float rs = rsqrtf(pq * (1.f / 64.f) - mu * mu + 1e-5f);
            u64 nmu2 = pack2(-mu, -mu), rs2 = pack2(rs, rs);
#pragma unroll
            for (int j = 0; j < 16; j++) {
                u64 cen = mul2(add2(z[j], nmu2), rs2);
                u64 v = fma2(cen, sgp[half * 16 + j], sbbp[half * 16 + j]);
                float lo, hi; unpack2(v, lo, hi);
                u32 whi, wlo; bfsplit2(lo, hi, whi, wlo);
                int ch = half * 32 + 2 * j;
                *(u32*)(pw_c + PO_EAH + el * 144 + ch * 2) = whi;
                *(u32*)(pw_c + PO_EAL + el * 144 + ch * 2) = wlo;
            }
        }
        // ---------- Pab gather: full 128-float rows, one row per iteration ----------
#pragma unroll 4
        for (int r = 0; r < 16; r++) {
            int d = dstp[e16 + r], s = srcp[e16 + r];
            float4 va = ((const float4*)(g_Pa + (size_t)d * 128))[lane];
            float4 vb = ((const float4*)(g_Pb + (size_t)s * 128))[lane];
            va.x += vb.x; va.y += vb.y; va.z += vb.z; va.w += vb.w;
            *(float4*)(pw_c + PO_PAB + r * 528 + lane * 16) = va;
        }
        __syncwarp();
        // ---------- GEMM1: D1[16e][128h] = EA @ W1c^T (3 split components) ----------
        float d1[16][4];
#pragma unroll
        for (int nt = 0; nt < 16; nt++) { d1[nt][0] = d1[nt][1] = d1[nt][2] = d1[nt][3] = 0.f; }
#pragma unroll
        for (int kc = 0; kc < 4; kc++) {
            u32 ah0, ah1, ah2, ah3, al0, al1, al2, al3;
            LDSM4(ah0, ah1, ah2, ah3, eah_b + kc * 32 + aoff_ea);
            LDSM4(al0, al1, al2, al3, eal_b + kc * 32 + aoff_ea);
#pragma unroll
            for (int nt = 0; nt < 16; nt++) {
                u32 bh0, bh1, bl0, bl1;
                u32 ba = sb + SO_W1TH + (u32)(nt * 1152 + kc * 32) + boff_w1;
                LDSM2(bh0, bh1, ba);
                LDSM2(bl0, bl1, ba + (SO_W1TL - SO_W1TH));
                MMA(d1[nt], ah0, ah1, ah2, ah3, bh0, bh1);
                MMA(d1[nt], ah0, ah1, ah2, ah3, bl0, bl1);
                MMA(d1[nt], al0, al1, al2, al3, bh0, bh1);
            }
        }
        // ---------- fused epilogue1 + GEMM2 ----------
        float d2[8][4];
#pragma unroll
        for (int ct = 0; ct < 8; ct++) { d2[ct][0] = d2[ct][1] = d2[ct][2] = d2[ct][3] = 0.f; }
#pragma unroll
        for (int hc = 0; hc < 8; hc++) {
            int n0 = 2 * hc, n1 = 2 * hc + 1;
            u32 slot = (hc & 1) ? 1536u : 0u;
#pragma unroll
            for (int rr = 0; rr < 2; rr++) {
                int r = r0 + 8 * rr;
                const char* prow = pw_c + PO_PAB + r * 528;
                float2 pA = *(const float2*)(prow + (hc * 16 + 2 * tp) * 4);
                float2 pB = *(const float2*)(prow + (hc * 16 + 8 + 2 * tp) * 4);
                float v0 = fmaxf(d1[n0][2 * rr]     + pA.x, 0.f);
                float v1 = fmaxf(d1[n0][2 * rr + 1] + pA.y, 0.f);
                float v2 = fmaxf(d1[n1][2 * rr]     + pB.x, 0.f);
                float v3 = fmaxf(d1[n1][2 * rr + 1] + pB.y, 0.f);
                u32 h01, l01, h23, l23;
                bfsplit2(v0, v1, h01, l01);
                bfsplit2(v2, v3, h23, l23);
                char* hrow = pw_c + PO_HB + slot + r * 48;
                *(u32*)(hrow + 4 * tp)            = h01;
                *(u32*)(hrow + 16 + 4 * tp)       = h23;
                *(u32*)(hrow + 768 + 4 * tp)      = l01;
                *(u32*)(hrow + 768 + 16 + 4 * tp) = l23;
            }
            __syncwarp();
            u32 ah0, ah1, ah2, ah3, al0, al1, al2, al3;
            LDSM4(ah0, ah1, ah2, ah3, hb_b + slot + aoff_hb);
            LDSM4(al0, al1, al2, al3, hb_b + slot + 768 + aoff_hb);
#pragma unroll
            for (int ct = 0; ct < 8; ct++) {
                u32 bh0, bh1, bl0, bl1;
                u32 ba = sb + SO_W2TH + (u32)(ct * 2176 + hc * 32) + boff_w2;
                LDSM2(bh0, bh1, ba);
                LDSM2(bl0, bl1, ba + (SO_W2TL - SO_W2TH));
                MMA(d2[ct], ah0, ah1, ah2, ah3, bh0, bh1);
                MMA(d2[ct], ah0, ah1, ah2, ah3, bl0, bl1);
                MMA(d2[ct], al0, al1, al2, al3, bh0, bh1);
            }
            __syncwarp();
        }
        // ---------- epilogue2: + b2, exp, RED, msg store ----------
#pragma unroll
        for (int rr = 0; rr < 2; rr++) {
            int r = r0 + 8 * rr;
            int e = e16 + r;
            int d = dstp[e];
            float* nd = ndb + (size_t)d * 128;
#pragma unroll
            for (int ct = 0; ct < 8; ct++) {
                int c0 = 8 * ct + 2 * tp;
                float m0 = d2[ct][2 * rr]     + sb2[c0];
                float m1 = d2[ct][2 * rr + 1] + sb2[c0 + 1];
                float E0 = __expf(m0 * t), E1 = __expf(m1 * t);
                asm volatile("red.global.add.v4.f32 [%0], {%1,%2,%3,%4};"
                             :: "l"(nd + 2 * c0), "f"(m0 * E0), "f"(E0),
                                "f"(m1 * E1), "f"(E1) : "memory");
                if (conv == 0)
                    *(float2*)(g_msg0 + (size_t)e * 64 + c0) = make_float2(m0, m1);
            }
        }
        __syncwarp();
    }
}

// ---------------- conv0 node finish ----------------
__global__ void __launch_bounds__(256) k_node0(
    const float* __restrict__ wr, const float* __restrict__ lg, const float* __restrict__ lb)
{
    extern __shared__ float sm[];
    for (int i = threadIdx.x; i < 64 * 64; i += blockDim.x) sm[i] = wr[i];
    __syncthreads();
    int l = threadIdx.x & 31;
    int warp = (blockIdx.x * blockDim.x + threadIdx.x) >> 5;
    int nwarps = (gridDim.x * blockDim.x) >> 5;
    float g0 = lg[l], g1 = lg[l + 32], b0 = lb[l], b1v = lb[l + 32];
    for (int n = warp; n < NN; n += nwarps) {
        float xe0 = g_xenc[n * 64 + l], xe1 = g_xenc[n * 64 + 32 + l];
        float r0 = 0.f, r1 = 0.f;
#pragma unroll 8
        for (int k = 0; k < 32; k++) {
            float xk = __shfl_sync(0xffffffffu, xe0, k);
            r0 = fmaf(xk, sm[k * 64 + l], r0);
            r1 = fmaf(xk, sm[k * 64 + l + 32], r1);
        }
#pragma unroll 8
        for (int k = 0; k < 32; k++) {
            float xk = __shfl_sync(0xffffffffu, xe1, k);
            r0 = fmaf(xk, sm[(k + 32) * 64 + l], r0);
            r1 = fmaf(xk, sm[(k + 32) * 64 + l + 32], r1);
        }
        float2 na = *(const float2*)(g_nd0 + (size_t)n * 128 + 2 * l);
        float2 nb = *(const float2*)(g_nd0 + (size_t)n * 128 + 64 + 2 * l);
        float x10 = ((na.y != 0.f) ? na.x / na.y : 0.f) + r0;
        float x11 = ((nb.y != 0.f) ? nb.x / nb.y : 0.f) + r1;
        g_x1[n * 64 + l] = x10;
        g_x1[n * 64 + l + 32] = x11;
        float mu = wsum(x10 + x11) * (1.f / 64.f);
        float sq = wsum(x10 * x10 + x11 * x11) * (1.f / 64.f);
        float rs = rsqrtf(sq - mu * mu + 1e-5f);
        g_h1[n * 64 + l]      = fmaxf((x10 - mu) * rs * g0 + b0, 0.f);
        g_h1[n * 64 + l + 32] = fmaxf((x11 - mu) * rs * g1 + b1v, 0.f);
    }
}

// ---------------- final node kernel ----------------
__global__ void __launch_bounds__(256) k_node1(
    const float* __restrict__ wr, float* __restrict__ out)
{
    extern __shared__ float sm[];
    for (int i = threadIdx.x; i < 64 * 64; i += blockDim.x) sm[i] = wr[i];
    __syncthreads();
    int l = threadIdx.x & 31;
    int warp = (blockIdx.x * blockDim.x + threadIdx.x) >> 5;
    int nwarps = (gridDim.x * blockDim.x) >> 5;
    for (int n = warp; n < NN; n += nwarps) {
        float he0 = g_h1[n * 64 + l], he1 = g_h1[n * 64 + 32 + l];
        float r0 = 0.f, r1 = 0.f;
#pragma unroll 8
        for (int k = 0; k < 32; k++) {
            float xk = __shfl_sync(0xffffffffu, he0, k);
            r0 = fmaf(xk, sm[k * 64 + l], r0);
            r1 = fmaf(xk, sm[k * 64 + l + 32], r1);
        }
#pragma unroll 8
        for (int k = 0; k < 32; k++) {
            float xk = __shfl_sync(0xffffffffu, he1, k);
            r0 = fmaf(xk, sm[(k + 32) * 64 + l], r0);
            r1 = fmaf(xk, sm[(k + 32) * 64 + l + 32], r1);
        }
        float2 na = *(const float2*)(g_nd1 + (size_t)n * 128 + 2 * l);
        float2 nb = *(const float2*)(g_nd1 + (size_t)n * 128 + 64 + 2 * l);
        float a0 = ((na.y != 0.f) ? na.x / na.y : 0.f) + r0;
        float a1 = ((nb.y != 0.f) ? nb.x / nb.y : 0.f) + r1;
        out[n * 64 + l]      = g_x1[n * 64 + l] + a0;
        out[n * 64 + l + 32] = g_x1[n * 64 + l + 32] + a1;
    }
}

extern "C" void kernel_launch(void* const* d_in, const int* in_sizes, int n_in,
                              void* d_out, int out_size)
{
    const float* x       = (const float*)d_in[0];
    const int*   ei      = (const int*)  d_in[1];
    const float* eattr   = (const float*)d_in[2];
    const float* enc_w   = (const float*)d_in[3];
    const float* enc_b   = (const float*)d_in[4];
    const float* enc_g   = (const float*)d_in[5];
    const float* enc_bb  = (const float*)d_in[6];
    const float* eenc_w  = (const float*)d_in[7];
    const float* eenc_b  = (const float*)d_in[8];
    const float* eenc_g  = (const float*)d_in[9];
    const float* eenc_bb = (const float*)d_in[10];
    const float* c0_w1   = (const float*)d_in[11];
    const float* c0_b1   = (const float*)d_in[12];
    const float* c0_w2   = (const float*)d_in[13];
    const float* c0_b2   = (const float*)d_in[14];
    const float* c0_wr   = (const float*)d_in[15];
    const float* c0_t    = (const float*)d_in[16];
    const float* l1_g    = (const float*)d_in[17];
    const float* l1_b    = (const float*)d_in[18];
    const float* l1_eg   = (const float*)d_in[19];
    const float* l1_eb   = (const float*)d_in[20];
    const float* c1_w1   = (const float*)d_in[21];
    const float* c1_b1   = (const float*)d_in[22];
    const float* c1_w2   = (const float*)d_in[23];
    const float* c1_b2   = (const float*)d_in[24];
    const float* c1_wr   = (const float*)d_in[25];
    const float* c1_t    = (const float*)d_in[26];
    float* out = (float*)d_out;

    cudaFuncSetAttribute(k_prep, cudaFuncAttributeMaxDynamicSharedMemorySize, 65536);
    cudaFuncSetAttribute(k_edge, cudaFuncAttributeMaxDynamicSharedMemorySize, SM_EDGE_BYTES);

    k_zero<<<2500, 256>>>();
    k_encode<<<320, 256, 24576>>>(x, enc_w, enc_b, enc_g, enc_bb);
    k_prep<<<444, 256, 65536>>>(0, c0_w1, c0_b1);
    k_edge<<<148, 256, SM_EDGE_BYTES>>>(0, ei, eattr, eenc_w, eenc_b, eenc_g, eenc_bb,
                                        c0_w1, c0_w2, c0_b2, c0_t);
    k_node0<<<320, 256, 16384>>>(c0_wr, l1_g, l1_b);
    k_prep<<<444, 256, 65536>>>(1, c1_w1, c1_b1);
    k_edge<<<148, 256, SM_EDGE_BYTES>>>(1, ei, eattr, eenc_w, eenc_b, l1_eg, l1_eb,
                                        c1_w1, c1_w2, c1_b2, c1_t);
    k_node1<<<320, 256, 16384>>>(c1_wr, out);
}

// round 8
// speedup vs baseline: 3.1828x; 1.1737x over previous
#include <cuda_runtime.h>
#include <cuda_bf16.h>
#include <math.h>

#define NN 20000
#define NE 640000

typedef unsigned long long u64;
typedef unsigned int u32;

// ---------------- scratch (device globals) ----------------
__device__ __align__(16) float g_xenc[NN * 64];
__device__ __align__(16) float g_x1[NN * 64];
__device__ __align__(16) float g_h1[NN * 64];
__device__ __align__(16) float g_Pa[NN * 128];
__device__ __align__(16) float g_Pb[NN * 128];
__device__ __align__(16) float g_nd0[NN * 128];
__device__ __align__(16) float g_nd1[NN * 128];
__device__ __align__(16) float g_msg0[(size_t)NE * 64];

// ---------------- f32x2 helpers ----------------
static __device__ __forceinline__ u64 fma2(u64 a, u64 b, u64 c) {
    u64 d; asm("fma.rn.f32x2 %0,%1,%2,%3;" : "=l"(d) : "l"(a), "l"(b), "l"(c)); return d;
}
static __device__ __forceinline__ u64 add2(u64 a, u64 b) {
    u64 d; asm("add.rn.f32x2 %0,%1,%2;" : "=l"(d) : "l"(a), "l"(b)); return d;
}
static __device__ __forceinline__ u64 mul2(u64 a, u64 b) {
    u64 d; asm("mul.rn.f32x2 %0,%1,%2;" : "=l"(d) : "l"(a), "l"(b)); return d;
}
static __device__ __forceinline__ u64 pack2(float lo, float hi) {
    u64 d; asm("mov.b64 %0,{%1,%2};" : "=l"(d) : "f"(lo), "f"(hi)); return d;
}
static __device__ __forceinline__ void unpack2(u64 a, float& lo, float& hi) {
    asm("mov.b64 {%0,%1},%2;" : "=f"(lo), "=f"(hi) : "l"(a));
}
static __device__ __forceinline__ float wsum(float v) {
#pragma unroll
    for (int o = 16; o; o >>= 1) v += __shfl_xor_sync(0xffffffffu, v, o);
    return v;
}
static __device__ __forceinline__ u32 smem_u32(const void* p) {
    u32 a; asm("{ .reg .u64 t; cvta.to.shared.u64 t, %1; cvt.u32.u64 %0, t; }" : "=r"(a) : "l"(p));
    return a;
}
static __device__ __forceinline__ void bfsplit2(float x, float y, u32& hi, u32& lo) {
    __nv_bfloat16 hx = __float2bfloat16(x), hy = __float2bfloat16(y);
    __nv_bfloat16 lx = __float2bfloat16(x - __bfloat162float(hx));
    __nv_bfloat16 ly = __float2bfloat16(y - __bfloat162float(hy));
    hi = (u32)__bfloat16_as_ushort(hx) | ((u32)__bfloat16_as_ushort(hy) << 16);
    lo = (u32)__bfloat16_as_ushort(lx) | ((u32)__bfloat16_as_ushort(ly) << 16);
}

#define LDSM4(r0, r1, r2, r3, a)                                             \
    asm volatile("ldmatrix.sync.aligned.m8n8.x4.shared.b16 {%0,%1,%2,%3}, [%4];" \
                 : "=r"(r0), "=r"(r1), "=r"(r2), "=r"(r3) : "r"(a))
#define MMA(d, a0, a1, a2, a3, b0, b1)                                       \
    asm volatile("mma.sync.aligned.m16n8k16.row.col.f32.bf16.bf16.f32 "      \
                 "{%0,%1,%2,%3}, {%4,%5,%6,%7}, {%8,%9}, {%0,%1,%2,%3};"     \
                 : "+f"((d)[0]), "+f"((d)[1]), "+f"((d)[2]), "+f"((d)[3])    \
                 : "r"(a0), "r"(a1), "r"(a2), "r"(a3), "r"(b0), "r"(b1))

// ---------------- smem layout (bytes) ----------------
#define SO_W1TH  0         // [128h][64k] bf16, stride 144  (18432)
#define SO_W1TL  18432
#define SO_W2TH  36864     // [64c][128k] bf16, stride 272  (17408)
#define SO_W2TL  54272
#define SO_SB2   71680     // float[64]
#define SO_SEB   71936     // u64[32]
#define SO_SGP   72192
#define SO_SBBP  72448
#define SO_EEW   72704     // u64[512]
#define SO_WARP  76800     // per-warp regions
#define PW_BYTES 7680
#define PO_EAH   0         // [16e][64k] bf16, stride 144 (2304)
#define PO_EAL   2304
#define PO_HB    4608      // 2 slots x (hi 768 + lo 768)
#define NWARPS_E 12
#define SM_EDGE_BYTES (76800 + NWARPS_E * PW_BYTES)   // 168960

// ---------------- zero accumulators ----------------
__global__ void k_zero() {
    int i = blockIdx.x * blockDim.x + threadIdx.x;
    if (i < NN * 128 / 4) {
        float4 z = make_float4(0.f, 0.f, 0.f, 0.f);
        ((float4*)g_nd0)[i] = z;
        ((float4*)g_nd1)[i] = z;
    }
}

// ---------------- node encoder ----------------
__global__ void __launch_bounds__(256) k_encode(
    const float* __restrict__ x, const float* __restrict__ enc_w,
    const float* __restrict__ enc_b, const float* __restrict__ enc_g,
    const float* __restrict__ enc_bb)
{
    extern __shared__ float sm[];
    for (int i = threadIdx.x; i < 96 * 64; i += blockDim.x) sm[i] = enc_w[i];
    __syncthreads();
    int l = threadIdx.x & 31;
    int warp = (blockIdx.x * blockDim.x + threadIdx.x) >> 5;
    int nwarps = (gridDim.x * blockDim.x) >> 5;
    float b0 = enc_b[l], b1v = enc_b[l + 32];
    float g0 = enc_g[l], g1 = enc_g[l + 32];
    float bb0 = enc_bb[l], bb1 = enc_bb[l + 32];
    for (int n = warp; n < NN; n += nwarps) {
        float xa = x[(size_t)n * 96 + l];
        float xb = x[(size_t)n * 96 + 32 + l];
        float xc = x[(size_t)n * 96 + 64 + l];
        float z0 = b0, z1 = b1v;
#pragma unroll 8
        for (int k = 0; k < 32; k++) {
            float xk = __shfl_sync(0xffffffffu, xa, k);
            z0 = fmaf(xk, sm[k * 64 + l], z0);
            z1 = fmaf(xk, sm[k * 64 + l + 32], z1);
        }
#pragma unroll 8
        for (int k = 0; k < 32; k++) {
            float xk = __shfl_sync(0xffffffffu, xb, k);
            z0 = fmaf(xk, sm[(k + 32) * 64 + l], z0);
            z1 = fmaf(xk, sm[(k + 32) * 64 + l + 32], z1);
        }
#pragma unroll 8
        for (int k = 0; k < 32; k++) {
            float xk = __shfl_sync(0xffffffffu, xc, k);
            z0 = fmaf(xk, sm[(k + 64) * 64 + l], z0);
            z1 = fmaf(xk, sm[(k + 64) * 64 + l + 32], z1);
        }
        float mu = wsum(z0 + z1) * (1.f / 64.f);
        float sq = wsum(z0 * z0 + z1 * z1) * (1.f / 64.f);
        float rs = rsqrtf(sq - mu * mu + 1e-5f);
        g_xenc[n * 64 + l]      = (z0 - mu) * rs * g0 + bb0;
        g_xenc[n * 64 + l + 32] = (z1 - mu) * rs * g1 + bb1;
    }
}

// ---------------- Pa/Pb precompute: 2 nodes per warp ----------------
__global__ void __launch_bounds__(256) k_prep(
    int use_h, const float* __restrict__ w1, const float* __restrict__ b1)
{
    extern __shared__ float sm[];
    for (int i = threadIdx.x; i < 128 * 128; i += blockDim.x) sm[i] = w1[i];
    __syncthreads();
    const float* xin = use_h ? g_h1 : g_xenc;
    int l = threadIdx.x & 31;
    int warp = (blockIdx.x * blockDim.x + threadIdx.x) >> 5;
    int nwarps = (gridDim.x * blockDim.x) >> 5;
    float4 bv = *(const float4*)(b1 + 4 * l);
    for (int n = warp * 2; n < NN; n += nwarps * 2) {
        float xA0 = xin[n * 64 + l],       xA1 = xin[n * 64 + 32 + l];
        float xB0 = xin[(n + 1) * 64 + l], xB1 = xin[(n + 1) * 64 + 32 + l];
        float4 paA = bv, paB = bv;
        float4 pbA = make_float4(0.f, 0.f, 0.f, 0.f);
        float4 pbB = make_float4(0.f, 0.f, 0.f, 0.f);
#pragma unroll 8
        for (int k = 0; k < 32; k++) {
            float kA = __shfl_sync(0xffffffffu, xA0, k);
            float kB = __shfl_sync(0xffffffffu, xB0, k);
            float4 wa = *(const float4*)(sm + k * 128 + 4 * l);
            float4 wb = *(const float4*)(sm + (k + 64) * 128 + 4 * l);
            paA.x = fmaf(kA, wa.x, paA.x); paA.y = fmaf(kA, wa.y, paA.y);
            paA.z = fmaf(kA, wa.z, paA.z); paA.w = fmaf(kA, wa.w, paA.w);
            pbA.x = fmaf(kA, wb.x, pbA.x); pbA.y = fmaf(kA, wb.y, pbA.y);
            pbA.z = fmaf(kA, wb.z, pbA.z); pbA.w = fmaf(kA, wb.w, pbA.w);
            paB.x = fmaf(kB, wa.x, paB.x); paB.y = fmaf(kB, wa.y, paB.y);
            paB.z = fmaf(kB, wa.z, paB.z); paB.w = fmaf(kB, wa.w, paB.w);
            pbB.x = fmaf(kB, wb.x, pbB.x); pbB.y = fmaf(kB, wb.y, pbB.y);
            pbB.z = fmaf(kB, wb.z, pbB.z); pbB.w = fmaf(kB, wb.w, pbB.w);
        }
#pragma unroll 8
        for (int k = 0; k < 32; k++) {
            float kA = __shfl_sync(0xffffffffu, xA1, k);
            float kB = __shfl_sync(0xffffffffu, xB1, k);
            float4 wa = *(const float4*)(sm + (k + 32) * 128 + 4 * l);
            float4 wb = *(const float4*)(sm + (k + 96) * 128 + 4 * l);
            paA.x = fmaf(kA, wa.x, paA.x); paA.y = fmaf(kA, wa.y, paA.y);
            paA.z = fmaf(kA, wa.z, paA.z); paA.w = fmaf(kA, wa.w, paA.w);
            pbA.x = fmaf(kA, wb.x, pbA.x); pbA.y = fmaf(kA, wb.y, pbA.y);
            pbA.z = fmaf(kA, wb.z, pbA.z); pbA.w = fmaf(kA, wb.w, pbA.w);
            paB.x = fmaf(kB, wa.x, paB.x); paB.y = fmaf(kB, wa.y, paB.y);
            paB.z = fmaf(kB, wa.z, paB.z); paB.w = fmaf(kB, wa.w, paB.w);
            pbB.x = fmaf(kB, wb.x, pbB.x); pbB.y = fmaf(kB, wb.y, pbB.y);
            pbB.z = fmaf(kB, wb.z, pbB.z); pbB.w = fmaf(kB, wb.w, pbB.w);
        }
        *(float4*)(g_Pa + (size_t)n * 128 + 4 * l) = paA;
        *(float4*)(g_Pb + (size_t)n * 128 + 4 * l) = pbA;
        *(float4*)(g_Pa + (size_t)(n + 1) * 128 + 4 * l) = paB;
        *(float4*)(g_Pb + (size_t)(n + 1) * 128 + 4 * l) = pbB;
    }
}

// ---------------- mma.sync edge kernel: 12 independent warps / CTA ----------------
__global__ void __launch_bounds__(384) k_edge(
    int conv, const int* __restrict__ ei, const float* __restrict__ eattr,
    const float* __restrict__ eenc_w, const float* __restrict__ eenc_b,
    const float* __restrict__ ln_g, const float* __restrict__ ln_b,
    const float* __restrict__ w1, const float* __restrict__ w2,
    const float* __restrict__ b2, const float* __restrict__ tptr)
{
    extern __shared__ __align__(1024) char smraw[];
    const u32 sb = smem_u32(smraw);
    int tid = threadIdx.x;
    int wid = tid >> 5, lane = tid & 31;

    u64* seb  = (u64*)(smraw + SO_SEB);
    u64* sgp  = (u64*)(smraw + SO_SGP);
    u64* sbbp = (u64*)(smraw + SO_SBBP);
    u64* eewp = (u64*)(smraw + SO_EEW);
    float* sb2 = (float*)(smraw + SO_SB2);

    // ---- one-time staging ----
    for (int i = tid; i < 64 * 128; i += 384) {        // W1c^T [h][k], stride 144
        int k = i >> 7, h = i & 127;
        float w = w1[(128 + k) * 128 + h];
        __nv_bfloat16 hi = __float2bfloat16(w);
        __nv_bfloat16 lo = __float2bfloat16(w - __bfloat162float(hi));
        *(__nv_bfloat16*)(smraw + SO_W1TH + h * 144 + k * 2) = hi;
        *(__nv_bfloat16*)(smraw + SO_W1TL + h * 144 + k * 2) = lo;
    }
    for (int i = tid; i < 128 * 64; i += 384) {        // W2^T [c][k], stride 272
        int k = i >> 6, c = i & 63;
        float w = w2[k * 64 + c];
        __nv_bfloat16 hi = __float2bfloat16(w);
        __nv_bfloat16 lo = __float2bfloat16(w - __bfloat162float(hi));
        *(__nv_bfloat16*)(smraw + SO_W2TH + c * 272 + k * 2) = hi;
        *(__nv_bfloat16*)(smraw + SO_W2TL + c * 272 + k * 2) = lo;
    }
    if (conv == 0) {
        for (int i = tid; i < 512; i += 384) eewp[i] = ((const u64*)eenc_w)[i];
        if (tid < 32) seb[tid] = ((const u64*)eenc_b)[tid];
    }
    if (tid < 32) {
        sgp[tid]  = ((const u64*)ln_g)[tid];
        sbbp[tid] = ((const u64*)ln_b)[tid];
    }
    if (tid < 64) sb2[tid] = b2[tid];
    __syncthreads();

    const float t = tptr[0];
    const int* srcp = ei;
    const int* dstp = ei + NE;
    float* ndb = conv ? g_nd1 : g_nd0;

    char* pw_c = smraw + SO_WARP + wid * PW_BYTES;
    const u32 pwb   = sb + SO_WARP + wid * PW_BYTES;
    const u32 eah_b = pwb + PO_EAH, eal_b = pwb + PO_EAL;
    const u32 hb_b  = pwb + PO_HB;

    const int el = lane >> 1, half = lane & 1;
    const int r0 = lane >> 2, tp = lane & 3;
    const int hl = ((lane >> 4) << 3) | (lane & 7);
    const int khalf = (lane >> 3) & 1;
    const u32 aoff_ea = (u32)((lane & 15) * 144 + (lane >> 4) * 16);
    const u32 boff4_w1 = (u32)(hl * 144 + khalf * 16);
    const u32 boff4_w2 = (u32)(hl * 272 + khalf * 16);
    const u32 aoff_hb = (u32)((lane & 15) * 48 + (lane >> 4) * 16);

    const int gw = blockIdx.x * NWARPS_E + wid;
    const int nw = gridDim.x * NWARPS_E;
    for (int g = gw; g < NE / 16; g += nw) {
        const int e16 = g * 16;
        // ---------- phase A: edge features + LN -> EA (bf16 split) ----------
        {
            u64 z[16];
            if (conv == 0) {
                float ar[16];
                const float4* ap = (const float4*)(eattr + (size_t)(e16 + el) * 16);
                *(float4*)&ar[0]  = ap[0]; *(float4*)&ar[4]  = ap[1];
                *(float4*)&ar[8]  = ap[2]; *(float4*)&ar[12] = ap[3];
#pragma unroll
                for (int j = 0; j < 16; j++) z[j] = seb[half * 16 + j];
#pragma unroll
                for (int k = 0; k < 16; k++) {
                    u64 av = pack2(ar[k], ar[k]);
                    const u64* wr_ = eewp + k * 32 + half * 16;
#pragma unroll
                    for (int j = 0; j < 16; j++) z[j] = fma2(av, wr_[j], z[j]);
                }
            } else {
                const u64* mp = (const u64*)(g_msg0 + (size_t)(e16 + el) * 64 + half * 32);
#pragma unroll
                for (int j = 0; j < 16; j++) z[j] = mp[j];
            }
            u64 s2 = 0ull, q2 = 0ull;
#pragma unroll
            for (int j = 0; j < 16; j++) { s2 = add2(s2, z[j]); q2 = fma2(z[j], z[j], q2); }
            float sl, sh2, ql, qh;
            unpack2(s2, sl, sh2); unpack2(q2, ql, qh);
            float ps = sl + sh2, pq = ql + qh;
            ps += __shfl_xor_sync(0xffffffffu, ps, 1);
            pq += __shfl_xor_sync(0xffffffffu, pq, 1);
            float mu = ps * (1.f / 64.f);
            float rs = rsqrtf(pq * (1.f / 64.f) - mu * mu + 1e-5f);
            u64 nmu2 = pack2(-mu, -mu), rs2 = pack2(rs, rs);
#pragma unroll
            for (int j = 0; j < 16; j++) {
                u64 cen = mul2(add2(z[j], nmu2), rs2);
                u64 v = fma2(cen, sgp[half * 16 + j], sbbp[half * 16 + j]);
                float lo, hi; unpack2(v, lo, hi);
                u32 whi, wlo; bfsplit2(lo, hi, whi, wlo);
                int ch = half * 32 + 2 * j;
                *(u32*)(pw_c + PO_EAH + el * 144 + ch * 2) = whi;
                *(u32*)(pw_c + PO_EAL + el * 144 + ch * 2) = wlo;
            }
        }
        // this thread's edge rows (r0 and r0+8)
        const int d0  = dstp[e16 + r0],     s0  = srcp[e16 + r0];
        const int d1v = dstp[e16 + r0 + 8], s1v = srcp[e16 + r0 + 8];
        __syncwarp();
        // ---------- GEMM1: D1[16e][128h] = EA @ W1c^T (paired-B LDSM4) ----------
        float d1[16][4];
#pragma unroll
        for (int nt = 0; nt < 16; nt++) { d1[nt][0] = d1[nt][1] = d1[nt][2] = d1[nt][3] = 0.f; }
#pragma unroll
        for (int kc = 0; kc < 4; kc++) {
            u32 ah0, ah1, ah2, ah3, al0, al1, al2, al3;
            LDSM4(ah0, ah1, ah2, ah3, eah_b + kc * 32 + aoff_ea);
            LDSM4(al0, al1, al2, al3, eal_b + kc * 32 + aoff_ea);
#pragma unroll
            for (int p = 0; p < 8; p++) {
                u32 bh0, bh1, bh2, bh3, bl0, bl1, bl2, bl3;
                u32 baH = sb + SO_W1TH + (u32)(p * 2304 + kc * 32) + boff4_w1;
                LDSM4(bh0, bh1, bh2, bh3, baH);
                LDSM4(bl0, bl1, bl2, bl3, baH + (SO_W1TL - SO_W1TH));
                MMA(d1[2 * p],     ah0, ah1, ah2, ah3, bh0, bh1);
                MMA(d1[2 * p],     ah0, ah1, ah2, ah3, bl0, bl1);
                MMA(d1[2 * p],     al0, al1, al2, al3, bh0, bh1);
                MMA(d1[2 * p + 1], ah0, ah1, ah2, ah3, bh2, bh3);
                MMA(d1[2 * p + 1], ah0, ah1, ah2, ah3, bl2, bl3);
                MMA(d1[2 * p + 1], al0, al1, al2, al3, bh2, bh3);
            }
        }
        // ---------- fused epilogue1 + GEMM2 (Pab direct from L2, prefetch 1 hc) ----------
        float d2[8][4];
#pragma unroll
        for (int ct = 0; ct < 8; ct++) { d2[ct][0] = d2[ct][1] = d2[ct][2] = d2[ct][3] = 0.f; }
        float2 pf[8];
        {
            int cb = 2 * tp;
            pf[0] = *(const float2*)(g_Pa + (size_t)d0 * 128 + cb);
            pf[1] = *(const float2*)(g_Pb + (size_t)s0 * 128 + cb);
            pf[2] = *(const float2*)(g_Pa + (size_t)d0 * 128 + cb + 8);
            pf[3] = *(const float2*)(g_Pb + (size_t)s0 * 128 + cb + 8);
            pf[4] = *(const float2*)(g_Pa + (size_t)d1v * 128 + cb);
            pf[5] = *(const float2*)(g_Pb + (size_t)s1v * 128 + cb);
            pf[6] = *(const float2*)(g_Pa + (size_t)d1v * 128 + cb + 8);
            pf[7] = *(const float2*)(g_Pb + (size_t)s1v * 128 + cb + 8);
        }
#pragma unroll
        for (int hc = 0; hc < 8; hc++) {
            float2 nf[8];
            if (hc < 7) {
                int cb = (hc + 1) * 16 + 2 * tp;
                nf[0] = *(const float2*)(g_Pa + (size_t)d0 * 128 + cb);
                nf[1] = *(const float2*)(g_Pb + (size_t)s0 * 128 + cb);
                nf[2] = *(const float2*)(g_Pa + (size_t)d0 * 128 + cb + 8);
                nf[3] = *(const float2*)(g_Pb + (size_t)s0 * 128 + cb + 8);
                nf[4] = *(const float2*)(g_Pa + (size_t)d1v * 128 + cb);
                nf[5] = *(const float2*)(g_Pb + (size_t)s1v * 128 + cb);
                nf[6] = *(const float2*)(g_Pa + (size_t)d1v * 128 + cb + 8);
                nf[7] = *(const float2*)(g_Pb + (size_t)s1v * 128 + cb + 8);
            }
            int n0 = 2 * hc, n1 = 2 * hc + 1;
            u32 slot = (hc & 1) ? 1536u : 0u;
#pragma unroll
            for (int rr = 0; rr < 2; rr++) {
                int r = r0 + 8 * rr;
                float pAx = pf[4 * rr].x + pf[4 * rr + 1].x;
                float pAy = pf[4 * rr].y + pf[4 * rr + 1].y;
                float pBx = pf[4 * rr + 2].x + pf[4 * rr + 3].x;
                float pBy = pf[4 * rr + 2].y + pf[4 * rr + 3].y;
                float v0 = fmaxf(d1[n0][2 * rr]     + pAx, 0.f);
                float v1 = fmaxf(d1[n0][2 * rr + 1] + pAy, 0.f);
                float v2 = fmaxf(d1[n1][2 * rr]     + pBx, 0.f);
                float v3 = fmaxf(d1[n1][2 * rr + 1] + pBy, 0.f);
                u32 h01, l01, h23, l23;
                bfsplit2(v0, v1, h01, l01);
                bfsplit2(v2, v3, h23, l23);
                char* hrow = pw_c + PO_HB + slot + r * 48;
                *(u32*)(hrow + 4 * tp)            = h01;
                *(u32*)(hrow + 16 + 4 * tp)       = h23;
                *(u32*)(hrow + 768 + 4 * tp)      = l01;
                *(u32*)(hrow + 768 + 16 + 4 * tp) = l23;
            }
            __syncwarp();
            u32 ah0, ah1, ah2, ah3, al0, al1, al2, al3;
            LDSM4(ah0, ah1, ah2, ah3, hb_b + slot + aoff_hb);
            LDSM4(al0, al1, al2, al3, hb_b + slot + 768 + aoff_hb);
#pragma unroll
            for (int q = 0; q < 4; q++) {
                u32 bh0, bh1, bh2, bh3, bl0, bl1, bl2, bl3;
                u32 baH = sb + SO_W2TH + (u32)(q * 4352 + hc * 32) + boff4_w2;
                LDSM4(bh0, bh1, bh2, bh3, baH);
                LDSM4(bl0, bl1, bl2, bl3, baH + (SO_W2TL - SO_W2TH));
                MMA(d2[2 * q],     ah0, ah1, ah2, ah3, bh0, bh1);
                MMA(d2[2 * q],     ah0, ah1, ah2, ah3, bl0, bl1);
                MMA(d2[2 * q],     al0, al1, al2, al3, bh0, bh1);
                MMA(d2[2 * q + 1], ah0, ah1, ah2, ah3, bh2, bh3);
                MMA(d2[2 * q + 1], ah0, ah1, ah2, ah3, bl2, bl3);
                MMA(d2[2 * q + 1], al0, al1, al2, al3, bh2, bh3);
            }
            __syncwarp();
            if (hc < 7) {
#pragma unroll
                for (int j = 0; j < 8; j++) pf[j] = nf[j];
            }
        }
        // ---------- epilogue2: + b2, exp, RED, msg store ----------
#pragma unroll
        for (int rr = 0; rr < 2; rr++) {
            int r = r0 + 8 * rr;
            int e = e16 + r;
            int d = rr ? d1v : d0;
            float* nd = ndb + (size_t)d * 128;
#pragma unroll
            for (int ct = 0; ct < 8; ct++) {
                int c0 = 8 * ct + 2 * tp;
                float m0 = d2[ct][2 * rr]     + sb2[c0];
                float m1 = d2[ct][2 * rr + 1] + sb2[c0 + 1];
                float E0 = __expf(m0 * t), E1 = __expf(m1 * t);
                asm volatile("red.global.add.v4.f32 [%0], {%1,%2,%3,%4};"
                             :: "l"(nd + 2 * c0), "f"(m0 * E0), "f"(E0),
                                "f"(m1 * E1), "f"(E1) : "memory");
                if (conv == 0)
                    *(float2*)(g_msg0 + (size_t)e * 64 + c0) = make_float2(m0, m1);
            }
        }
        __syncwarp();
    }
}

// ---------------- conv0 node finish ----------------
__global__ void __launch_bounds__(256) k_node0(
    const float* __restrict__ wr, const float* __restrict__ lg, const float* __restrict__ lb)
{
    extern __shared__ float sm[];
    for (int i = threadIdx.x; i < 64 * 64; i += blockDim.x) sm[i] = wr[i];
    __syncthreads();
    int l = threadIdx.x & 31;
    int warp = (blockIdx.x * blockDim.x + threadIdx.x) >> 5;
    int nwarps = (gridDim.x * blockDim.x) >> 5;
    float g0 = lg[l], g1 = lg[l + 32], b0 = lb[l], b1v = lb[l + 32];
    for (int n = warp; n < NN; n += nwarps) {
        float xe0 = g_xenc[n * 64 + l], xe1 = g_xenc[n * 64 + 32 + l];
        float r0 = 0.f, r1 = 0.f;
#pragma unroll 8
        for (int k = 0; k < 32; k++) {
            float xk = __shfl_sync(0xffffffffu, xe0, k);
            r0 = fmaf(xk, sm[k * 64 + l], r0);
            r1 = fmaf(xk, sm[k * 64 + l + 32], r1);
        }
#pragma unroll 8
        for (int k = 0; k < 32; k++) {
            float xk = __shfl_sync(0xffffffffu, xe1, k);
            r0 = fmaf(xk, sm[(k + 32) * 64 + l], r0);
            r1 = fmaf(xk, sm[(k + 32) * 64 + l + 32], r1);
        }
        float2 na = *(const float2*)(g_nd0 + (size_t)n * 128 + 2 * l);
        float2 nb = *(const float2*)(g_nd0 + (size_t)n * 128 + 64 + 2 * l);
        float x10 = ((na.y != 0.f) ? na.x / na.y : 0.f) + r0;
        float x11 = ((nb.y != 0.f) ? nb.x / nb.y : 0.f) + r1;
        g_x1[n * 64 + l] = x10;
        g_x1[n * 64 + l + 32] = x11;
        float mu = wsum(x10 + x11) * (1.f / 64.f);
        float sq = wsum(x10 * x10 + x11 * x11) * (1.f / 64.f);
        float rs = rsqrtf(sq - mu * mu + 1e-5f);
        g_h1[n * 64 + l]      = fmaxf((x10 - mu) * rs * g0 + b0, 0.f);
        g_h1[n * 64 + l + 32] = fmaxf((x11 - mu) * rs * g1 + b1v, 0.f);
    }
}

// ---------------- final node kernel ----------------
__global__ void __launch_bounds__(256) k_node1(
    const float* __restrict__ wr, float* __restrict__ out)
{
    extern __shared__ float sm[];
    for (int i = threadIdx.x; i < 64 * 64; i += blockDim.x) sm[i] = wr[i];
    __syncthreads();
    int l = threadIdx.x & 31;
    int warp = (blockIdx.x * blockDim.x + threadIdx.x) >> 5;
    int nwarps = (gridDim.x * blockDim.x) >> 5;
    for (int n = warp; n < NN; n += nwarps) {
        float he0 = g_h1[n * 64 + l], he1 = g_h1[n * 64 + 32 + l];
        float r0 = 0.f, r1 = 0.f;
#pragma unroll 8
        for (int k = 0; k < 32; k++) {
            float xk = __shfl_sync(0xffffffffu, he0, k);
            r0 = fmaf(xk, sm[k * 64 + l], r0);
            r1 = fmaf(xk, sm[k * 64 + l + 32], r1);
        }
#pragma unroll 8
        for (int k = 0; k < 32; k++) {
            float xk = __shfl_sync(0xffffffffu, he1, k);
            r0 = fmaf(xk, sm[(k + 32) * 64 + l], r0);
            r1 = fmaf(xk, sm[(k + 32) * 64 + l + 32], r1);
        }
        float2 na = *(const float2*)(g_nd1 + (size_t)n * 128 + 2 * l);
        float2 nb = *(const float2*)(g_nd1 + (size_t)n * 128 + 64 + 2 * l);
        float a0 = ((na.y != 0.f) ? na.x / na.y : 0.f) + r0;
        float a1 = ((nb.y != 0.f) ? nb.x / nb.y : 0.f) + r1;
        out[n * 64 + l]      = g_x1[n * 64 + l] + a0;
        out[n * 64 + l + 32] = g_x1[n * 64 + l + 32] + a1;
    }
}

extern "C" void kernel_launch(void* const* d_in, const int* in_sizes, int n_in,
                              void* d_out, int out_size)
{
    const float* x       = (const float*)d_in[0];
    const int*   ei      = (const int*)  d_in[1];
    const float* eattr   = (const float*)d_in[2];
    const float* enc_w   = (const float*)d_in[3];
    const float* enc_b   = (const float*)d_in[4];
    const float* enc_g   = (const float*)d_in[5];
    const float* enc_bb  = (const float*)d_in[6];
    const float* eenc_w  = (const float*)d_in[7];
    const float* eenc_b  = (const float*)d_in[8];
    const float* eenc_g  = (const float*)d_in[9];
    const float* eenc_bb = (const float*)d_in[10];
    const float* c0_w1   = (const float*)d_in[11];
    const float* c0_b1   = (const float*)d_in[12];
    const float* c0_w2   = (const float*)d_in[13];
    const float* c0_b2   = (const float*)d_in[14];
    const float* c0_wr   = (const float*)d_in[15];
    const float* c0_t    = (const float*)d_in[16];
    const float* l1_g    = (const float*)d_in[17];
    const float* l1_b    = (const float*)d_in[18];
    const float* l1_eg   = (const float*)d_in[19];
    const float* l1_eb   = (const float*)d_in[20];
    const float* c1_w1   = (const float*)d_in[21];
    const float* c1_b1   = (const float*)d_in[22];
    const float* c1_w2   = (const float*)d_in[23];
    const float* c1_b2   = (const float*)d_in[24];
    const float* c1_wr   = (const float*)d_in[25];
    const float* c1_t    = (const float*)d_in[26];
    float* out = (float*)d_out;

    cudaFuncSetAttribute(k_prep, cudaFuncAttributeMaxDynamicSharedMemorySize, 65536);
    cudaFuncSetAttribute(k_edge, cudaFuncAttributeMaxDynamicSharedMemorySize, SM_EDGE_BYTES);

    k_zero<<<2500, 256>>>();
    k_encode<<<320, 256, 24576>>>(x, enc_w, enc_b, enc_g, enc_bb);
    k_prep<<<444, 256, 65536>>>(0, c0_w1, c0_b1);
    k_edge<<<148, 384, SM_EDGE_BYTES>>>(0, ei, eattr, eenc_w, eenc_b, eenc_g, eenc_bb,
                                        c0_w1, c0_w2, c0_b2, c0_t);
    k_node0<<<320, 256, 16384>>>(c0_wr, l1_g, l1_b);
    k_prep<<<444, 256, 65536>>>(1, c1_w1, c1_b1);
    k_edge<<<148, 384, SM_EDGE_BYTES>>>(1, ei, eattr, eenc_w, eenc_b, l1_eg, l1_eb,
                                        c1_w1, c1_w2, c1_b2, c1_t);
    k_node1<<<320, 256, 16384>>>(c1_wr, out);
}